// round 3
// baseline (speedup 1.0000x reference)
#include <cuda_runtime.h>
#include <math.h>

// Problem constants: feat [65536, 256], n_per_graph = 512 -> B = 128, d = 256.
#define NB   128
#define NPG  512
#define DIM  256
#define DD   (DIM*DIM)
#define BD   (NB*DD)
#define NOISE_RATE 0.01f

// Scratch (allocation-free rule: device globals)
__device__ float g_A[BD];
__device__ float g_Y0[BD];
__device__ float g_Y1[BD];
__device__ float g_Z0[BD];
__device__ float g_Z1[BD];
__device__ float g_T[BD];
__device__ float g_mean[NB*DIM];
__device__ float g_v[NB*DIM];
__device__ float g_norm[NB];

// ---------------------------------------------------------------------------
// tf32 helpers: 2-term split (3xTF32 scheme)
// ---------------------------------------------------------------------------
__device__ __forceinline__ unsigned tf32r(float x) {
    unsigned r; asm("cvt.rna.tf32.f32 %0, %1;" : "=r"(r) : "f"(x)); return r;
}
// returns (hi, lo) both already tf32-rounded, stored as float bit patterns
__device__ __forceinline__ float2 splitf(float x) {
    unsigned hb = tf32r(x);
    float hf = __uint_as_float(hb);
    unsigned lb = tf32r(x - hf);
    return make_float2(hf, __uint_as_float(lb));
}

__device__ __forceinline__ void mma8(float* c,
                                     unsigned a0, unsigned a1, unsigned a2, unsigned a3,
                                     unsigned b0, unsigned b1) {
    asm volatile(
        "mma.sync.aligned.m16n8k8.row.col.f32.tf32.tf32.f32 "
        "{%0,%1,%2,%3}, {%4,%5,%6,%7}, {%8,%9}, {%0,%1,%2,%3};"
        : "+f"(c[0]), "+f"(c[1]), "+f"(c[2]), "+f"(c[3])
        : "r"(a0), "r"(a1), "r"(a2), "r"(a3), "r"(b0), "r"(b1));
}

// ---------------------------------------------------------------------------
// mean + trace in one pass: one block per batch, one thread per column.
// trace(cov) = (sum ||v||^2 - N*||mean||^2) / (N-1)
// ---------------------------------------------------------------------------
__global__ void mean_kernel(const float* __restrict__ feat,
                            const float* __restrict__ noise) {
    int b = blockIdx.x, c = threadIdx.x;
    const float* F  = feat  + (size_t)b * NPG * DIM + c;
    const float* Nz = noise + (size_t)b * NPG * DIM + c;
    float s = 0.f, q = 0.f;
    #pragma unroll 8
    for (int n = 0; n < NPG; ++n) {
        float v = F[(size_t)n * DIM] + NOISE_RATE * Nz[(size_t)n * DIM];
        s += v; q += v * v;
    }
    float m = s * (1.f / NPG);
    g_mean[b * DIM + c] = m;
    float t = q - (float)NPG * m * m;   // Σ diff^2 for this column
    // block reduce over 256 threads
    #pragma unroll
    for (int o = 16; o; o >>= 1) t += __shfl_xor_sync(0xffffffffu, t, o);
    __shared__ float sm[8];
    if ((c & 31) == 0) sm[c >> 5] = t;
    __syncthreads();
    if (c == 0) {
        float tot = 0.f;
        #pragma unroll
        for (int w = 0; w < 8; w++) tot += sm[w];
        g_norm[b] = tot * (1.f / (NPG - 1));
    }
}

// ---------------------------------------------------------------------------
// covariance via tf32 MMA, fused with normalization and Z0 construction.
// A_out = cov/trace ; Z0 = 1.5I - 0.5*A_out
// 128x128 tile per CTA, K=512 in BK=16 chunks, register-prefetch pipeline.
// ---------------------------------------------------------------------------
__global__ void __launch_bounds__(256) cov_tc(const float* __restrict__ feat,
                                              const float* __restrict__ noise) {
    int b  = blockIdx.z;
    int i0 = blockIdx.y * 128, j0 = blockIdx.x * 128;
    __shared__ float2 As2[16][137];
    __shared__ float2 Bs2[16][137];
    __shared__ float mi[128], mj[128];

    int tid = threadIdx.x, lane = tid & 31, w = tid >> 5;
    int wm = w >> 2, wn = w & 3;
    int gid = lane >> 2, tig = lane & 3;

    if (tid < 128) mi[tid] = g_mean[b * DIM + i0 + tid];
    else           mj[tid - 128] = g_mean[b * DIM + j0 + tid - 128];
    __syncthreads();

    float acc[4][4][4];
    #pragma unroll
    for (int mt = 0; mt < 4; mt++)
        #pragma unroll
        for (int nt = 0; nt < 4; nt++)
            #pragma unroll
            for (int k = 0; k < 4; k++) acc[mt][nt][k] = 0.f;

    const float* F  = feat  + (size_t)b * NPG * DIM;
    const float* Nz = noise + (size_t)b * NPG * DIM;

    int kr[2], cq[2];
    #pragma unroll
    for (int i = 0; i < 2; i++) { int idx = tid * 2 + i; kr[i] = idx >> 5; cq[i] = idx & 31; }

    float4 fa[2], na[2], fb[2], nb[2];
    #pragma unroll
    for (int i = 0; i < 2; i++) {
        size_t rowoff = (size_t)kr[i] * DIM;
        fa[i] = *(const float4*)&F [rowoff + i0 + cq[i] * 4];
        na[i] = *(const float4*)&Nz[rowoff + i0 + cq[i] * 4];
        fb[i] = *(const float4*)&F [rowoff + j0 + cq[i] * 4];
        nb[i] = *(const float4*)&Nz[rowoff + j0 + cq[i] * 4];
    }

    for (int kt = 0; kt < NPG; kt += 16) {
        __syncthreads();
        #pragma unroll
        for (int i = 0; i < 2; i++) {
            float af[4] = {fa[i].x + NOISE_RATE * na[i].x, fa[i].y + NOISE_RATE * na[i].y,
                           fa[i].z + NOISE_RATE * na[i].z, fa[i].w + NOISE_RATE * na[i].w};
            float bf[4] = {fb[i].x + NOISE_RATE * nb[i].x, fb[i].y + NOISE_RATE * nb[i].y,
                           fb[i].z + NOISE_RATE * nb[i].z, fb[i].w + NOISE_RATE * nb[i].w};
            #pragma unroll
            for (int j = 0; j < 4; j++) {
                As2[kr[i]][cq[i] * 4 + j] = splitf(af[j] - mi[cq[i] * 4 + j]);
                Bs2[kr[i]][cq[i] * 4 + j] = splitf(bf[j] - mj[cq[i] * 4 + j]);
            }
        }
        __syncthreads();
        if (kt + 16 < NPG) {
            #pragma unroll
            for (int i = 0; i < 2; i++) {
                size_t rowoff = (size_t)(kt + 16 + kr[i]) * DIM;
                fa[i] = *(const float4*)&F [rowoff + i0 + cq[i] * 4];
                na[i] = *(const float4*)&Nz[rowoff + i0 + cq[i] * 4];
                fb[i] = *(const float4*)&F [rowoff + j0 + cq[i] * 4];
                nb[i] = *(const float4*)&Nz[rowoff + j0 + cq[i] * 4];
            }
        }
        #pragma unroll
        for (int kk = 0; kk < 16; kk += 8) {
            unsigned ah[4][4], al[4][4], bh[4][2], bl[4][2];
            #pragma unroll
            for (int mt = 0; mt < 4; mt++) {
                int r = wm * 64 + mt * 16 + gid;
                float2 p0 = As2[kk + tig][r];
                float2 p1 = As2[kk + tig][r + 8];
                float2 p2 = As2[kk + tig + 4][r];
                float2 p3 = As2[kk + tig + 4][r + 8];
                ah[mt][0] = __float_as_uint(p0.x); al[mt][0] = __float_as_uint(p0.y);
                ah[mt][1] = __float_as_uint(p1.x); al[mt][1] = __float_as_uint(p1.y);
                ah[mt][2] = __float_as_uint(p2.x); al[mt][2] = __float_as_uint(p2.y);
                ah[mt][3] = __float_as_uint(p3.x); al[mt][3] = __float_as_uint(p3.y);
            }
            #pragma unroll
            for (int nt = 0; nt < 4; nt++) {
                int c = wn * 32 + nt * 8 + gid;
                float2 q0 = Bs2[kk + tig][c];
                float2 q1 = Bs2[kk + tig + 4][c];
                bh[nt][0] = __float_as_uint(q0.x); bl[nt][0] = __float_as_uint(q0.y);
                bh[nt][1] = __float_as_uint(q1.x); bl[nt][1] = __float_as_uint(q1.y);
            }
            #pragma unroll
            for (int mt = 0; mt < 4; mt++)
                #pragma unroll
                for (int nt = 0; nt < 4; nt++) {
                    mma8(acc[mt][nt], ah[mt][0], ah[mt][1], ah[mt][2], ah[mt][3], bh[nt][0], bh[nt][1]);
                    mma8(acc[mt][nt], ah[mt][0], ah[mt][1], ah[mt][2], ah[mt][3], bl[nt][0], bl[nt][1]);
                    mma8(acc[mt][nt], al[mt][0], al[mt][1], al[mt][2], al[mt][3], bh[nt][0], bh[nt][1]);
                }
        }
    }
    float sc = 1.f / ((NPG - 1) * g_norm[b]);
    float* Av = g_A  + (size_t)b * DD;
    float* Zv = g_Z0 + (size_t)b * DD;
    #pragma unroll
    for (int mt = 0; mt < 4; mt++) {
        int r = i0 + wm * 64 + mt * 16 + gid;
        #pragma unroll
        for (int nt = 0; nt < 4; nt++) {
            int c = j0 + wn * 32 + nt * 8 + tig * 2;
            float v0 = acc[mt][nt][0] * sc, v1 = acc[mt][nt][1] * sc;
            float v2 = acc[mt][nt][2] * sc, v3 = acc[mt][nt][3] * sc;
            *(float2*)&Av[(size_t)r * DIM + c]       = make_float2(v0, v1);
            *(float2*)&Av[(size_t)(r + 8) * DIM + c] = make_float2(v2, v3);
            float z0 = (r == c     ? 1.5f : 0.f) - 0.5f * v0;
            float z1 = (r == c + 1 ? 1.5f : 0.f) - 0.5f * v1;
            float z2 = (r + 8 == c     ? 1.5f : 0.f) - 0.5f * v2;
            float z3 = (r + 8 == c + 1 ? 1.5f : 0.f) - 0.5f * v3;
            *(float2*)&Zv[(size_t)r * DIM + c]       = make_float2(z0, z1);
            *(float2*)&Zv[(size_t)(r + 8) * DIM + c] = make_float2(z2, z3);
        }
    }
}

// ---------------------------------------------------------------------------
// batched 256x256x256 GEMM via tf32 MMA (3xTF32 split).
// MODE 0: C = A@B.  MODE 1: C = 1.5I - 0.5*(A@B)
// 128x128 tile per CTA, BK=16, register-prefetch pipeline.
// ---------------------------------------------------------------------------
template <int MODE>
__global__ void __launch_bounds__(256) gemm_tc(const float* __restrict__ Ag,
                                               const float* __restrict__ Bg,
                                               float* __restrict__ Cg) {
    int b = blockIdx.z;
    const float* A  = Ag + (size_t)b * DD;
    const float* Bm = Bg + (size_t)b * DD;
    float* C = Cg + (size_t)b * DD;
    int m0 = blockIdx.y * 128, n0 = blockIdx.x * 128;

    __shared__ float2 As2[16][137];
    __shared__ float2 Bs2[16][137];

    int tid = threadIdx.x, lane = tid & 31, w = tid >> 5;
    int wm = w >> 2, wn = w & 3;
    int gid = lane >> 2, tig = lane & 3;

    float acc[4][4][4];
    #pragma unroll
    for (int mt = 0; mt < 4; mt++)
        #pragma unroll
        for (int nt = 0; nt < 4; nt++)
            #pragma unroll
            for (int k = 0; k < 4; k++) acc[mt][nt][k] = 0.f;

    int arow[2], aq[2], bk_[2], bc[2];
    #pragma unroll
    for (int i = 0; i < 2; i++) {
        int idx = tid * 2 + i;
        arow[i] = idx >> 2; aq[i] = idx & 3;
        bk_[i] = idx >> 5;  bc[i] = idx & 31;
    }
    float4 av[2], bv[2];
    #pragma unroll
    for (int i = 0; i < 2; i++) {
        av[i] = *(const float4*)&A [(size_t)(m0 + arow[i]) * DIM + aq[i] * 4];
        bv[i] = *(const float4*)&Bm[(size_t)bk_[i] * DIM + n0 + bc[i] * 4];
    }

    for (int kt = 0; kt < DIM; kt += 16) {
        __syncthreads();
        #pragma unroll
        for (int i = 0; i < 2; i++) {
            float af[4] = {av[i].x, av[i].y, av[i].z, av[i].w};
            float bf[4] = {bv[i].x, bv[i].y, bv[i].z, bv[i].w};
            #pragma unroll
            for (int j = 0; j < 4; j++) {
                As2[aq[i] * 4 + j][arow[i]] = splitf(af[j]);   // [k][m]
                Bs2[bk_[i]][bc[i] * 4 + j]  = splitf(bf[j]);   // [k][n]
            }
        }
        __syncthreads();
        if (kt + 16 < DIM) {
            #pragma unroll
            for (int i = 0; i < 2; i++) {
                av[i] = *(const float4*)&A [(size_t)(m0 + arow[i]) * DIM + kt + 16 + aq[i] * 4];
                bv[i] = *(const float4*)&Bm[(size_t)(kt + 16 + bk_[i]) * DIM + n0 + bc[i] * 4];
            }
        }
        #pragma unroll
        for (int kk = 0; kk < 16; kk += 8) {
            unsigned ah[4][4], al[4][4], bh[4][2], bl[4][2];
            #pragma unroll
            for (int mt = 0; mt < 4; mt++) {
                int r = wm * 64 + mt * 16 + gid;
                float2 p0 = As2[kk + tig][r];
                float2 p1 = As2[kk + tig][r + 8];
                float2 p2 = As2[kk + tig + 4][r];
                float2 p3 = As2[kk + tig + 4][r + 8];
                ah[mt][0] = __float_as_uint(p0.x); al[mt][0] = __float_as_uint(p0.y);
                ah[mt][1] = __float_as_uint(p1.x); al[mt][1] = __float_as_uint(p1.y);
                ah[mt][2] = __float_as_uint(p2.x); al[mt][2] = __float_as_uint(p2.y);
                ah[mt][3] = __float_as_uint(p3.x); al[mt][3] = __float_as_uint(p3.y);
            }
            #pragma unroll
            for (int nt = 0; nt < 4; nt++) {
                int c = wn * 32 + nt * 8 + gid;
                float2 q0 = Bs2[kk + tig][c];
                float2 q1 = Bs2[kk + tig + 4][c];
                bh[nt][0] = __float_as_uint(q0.x); bl[nt][0] = __float_as_uint(q0.y);
                bh[nt][1] = __float_as_uint(q1.x); bl[nt][1] = __float_as_uint(q1.y);
            }
            #pragma unroll
            for (int mt = 0; mt < 4; mt++)
                #pragma unroll
                for (int nt = 0; nt < 4; nt++) {
                    mma8(acc[mt][nt], ah[mt][0], ah[mt][1], ah[mt][2], ah[mt][3], bh[nt][0], bh[nt][1]);
                    mma8(acc[mt][nt], ah[mt][0], ah[mt][1], ah[mt][2], ah[mt][3], bl[nt][0], bl[nt][1]);
                    mma8(acc[mt][nt], al[mt][0], al[mt][1], al[mt][2], al[mt][3], bh[nt][0], bh[nt][1]);
                }
        }
    }
    #pragma unroll
    for (int mt = 0; mt < 4; mt++) {
        int r = m0 + wm * 64 + mt * 16 + gid;
        #pragma unroll
        for (int nt = 0; nt < 4; nt++) {
            int c = n0 + wn * 32 + nt * 8 + tig * 2;
            float v0 = acc[mt][nt][0], v1 = acc[mt][nt][1];
            float v2 = acc[mt][nt][2], v3 = acc[mt][nt][3];
            if (MODE == 1) {
                v0 = (r == c     ? 1.5f : 0.f) - 0.5f * v0;
                v1 = (r == c + 1 ? 1.5f : 0.f) - 0.5f * v1;
                v2 = (r + 8 == c     ? 1.5f : 0.f) - 0.5f * v2;
                v3 = (r + 8 == c + 1 ? 1.5f : 0.f) - 0.5f * v3;
            }
            *(float2*)&C[(size_t)r * DIM + c]       = make_float2(v0, v1);
            *(float2*)&C[(size_t)(r + 8) * DIM + c] = make_float2(v2, v3);
        }
    }
}

// ---------------------------------------------------------------------------
// out[b] = scale * (M[b] @ vin[b]).  scale = sqrt(norm[b]) if useScale.
// ---------------------------------------------------------------------------
__global__ void matvec_kernel(const float* __restrict__ M,
                              const float* __restrict__ vin,
                              float* __restrict__ outp, int useScale) {
    int b = blockIdx.x;
    __shared__ float vs[DIM];
    int tid = threadIdx.x;
    vs[tid] = vin[b * DIM + tid];
    __syncthreads();
    int warp = tid >> 5, lane = tid & 31;
    const float* Mb = M + (size_t)b * DD;
    float scale = useScale ? sqrtf(g_norm[b]) : 1.f;
    for (int r = warp; r < DIM; r += 8) {
        float s = 0.f;
        #pragma unroll
        for (int c = lane; c < DIM; c += 32) s += Mb[(size_t)r * DIM + c] * vs[c];
        #pragma unroll
        for (int o = 16; o; o >>= 1) s += __shfl_xor_sync(0xffffffffu, s, o);
        if (lane == 0) outp[b * DIM + r] = s * scale;
    }
}

// ---------------------------------------------------------------------------
extern "C" void kernel_launch(void* const* d_in, const int* in_sizes, int n_in,
                              void* d_out, int out_size) {
    const float* feat  = (const float*)d_in[0];
    const float* noise = (const float*)d_in[1];
    float* out = (float*)d_out;

    float *A, *Y0, *Y1, *Z0, *Z1, *T, *Mean, *Vv;
    cudaGetSymbolAddress((void**)&A,    g_A);
    cudaGetSymbolAddress((void**)&Y0,   g_Y0);
    cudaGetSymbolAddress((void**)&Y1,   g_Y1);
    cudaGetSymbolAddress((void**)&Z0,   g_Z0);
    cudaGetSymbolAddress((void**)&Z1,   g_Z1);
    cudaGetSymbolAddress((void**)&T,    g_T);
    cudaGetSymbolAddress((void**)&Mean, g_mean);
    cudaGetSymbolAddress((void**)&Vv,   g_v);

    mean_kernel<<<NB, DIM>>>(feat, noise);          // mean + trace
    cov_tc<<<dim3(2, 2, NB), 256>>>(feat, noise);   // A = cov/tr, Z0 = 1.5I-0.5A

    dim3 gg(2, 2, NB);
    gemm_tc<0><<<gg, 256>>>(A, Z0, Y0);             // Y = A @ Z0

    float* Yc[2] = {Y0, Y1};
    float* Zc[2] = {Z0, Z1};
    int cur = 0;
    for (int it = 0; it < 3; ++it) {                // ITERN=5 -> 3 middle iters
        gemm_tc<1><<<gg, 256>>>(Zc[cur], Yc[cur], T);       // T = 1.5I - 0.5*Z@Y
        gemm_tc<0><<<gg, 256>>>(Yc[cur], T, Yc[1 - cur]);   // Y' = Y@T
        gemm_tc<0><<<gg, 256>>>(T, Zc[cur], Zc[1 - cur]);   // Z' = T@Z
        cur ^= 1;
    }
    gemm_tc<1><<<gg, 256>>>(Zc[cur], Yc[cur], T);   // S = 1.5I - 0.5*Z@Y
    matvec_kernel<<<NB, DIM>>>(T, Mean, Vv, 0);     // v = S @ mean
    matvec_kernel<<<NB, DIM>>>(Yc[cur], Vv, out, 1); // out = sqrt(norm)*Y@v
}

// round 5
// speedup vs baseline: 2.4865x; 2.4865x over previous
#include <cuda_runtime.h>
#include <cuda_bf16.h>
#include <math.h>
#include <stdint.h>

// Problem constants: feat [65536, 256], n_per_graph = 512 -> B = 128, d = 256.
#define NB   128
#define NPG  512
#define DIM  256
#define DD   (DIM*DIM)
#define BD   (NB*DD)
#define NOISE_RATE 0.01f

// Scratch (allocation-free rule: device globals)
__device__ float g_A[BD];
__device__ float g_Y0[BD];
__device__ float g_Y1[BD];
__device__ float g_Z0[BD];
__device__ float g_Z1[BD];
__device__ float g_T[BD];
__device__ float g_mean[NB*DIM];
__device__ float g_v[NB*DIM];
__device__ float g_norm[NB];

// ---------------------------------------------------------------------------
// helpers
// ---------------------------------------------------------------------------
__device__ __forceinline__ uint32_t smem_u32(const void* p) {
    uint32_t a;
    asm("{ .reg .u64 t; cvta.to.shared.u64 t, %1; cvt.u32.u64 %0, t; }" : "=r"(a) : "l"(p));
    return a;
}
__device__ __forceinline__ void ldm4(uint32_t* r, uint32_t a) {
    asm volatile("ldmatrix.sync.aligned.m8n8.x4.shared.b16 {%0,%1,%2,%3}, [%4];"
                 : "=r"(r[0]), "=r"(r[1]), "=r"(r[2]), "=r"(r[3]) : "r"(a));
}
__device__ __forceinline__ void mma16816(float* c, const uint32_t* a, const uint32_t* bq) {
    asm volatile("mma.sync.aligned.m16n8k16.row.col.f32.bf16.bf16.f32 "
                 "{%0,%1,%2,%3}, {%4,%5,%6,%7}, {%8,%9}, {%0,%1,%2,%3};"
                 : "+f"(c[0]), "+f"(c[1]), "+f"(c[2]), "+f"(c[3])
                 : "r"(a[0]), "r"(a[1]), "r"(a[2]), "r"(a[3]), "r"(bq[0]), "r"(bq[1]));
}
// bf16 2-term split of 4 floats -> packed h (2x u32) and m (2x u32)
__device__ __forceinline__ void split4(float4 v, uint32_t& h0, uint32_t& h1,
                                       uint32_t& q0, uint32_t& q1) {
    __nv_bfloat16 a = __float2bfloat16_rn(v.x);
    __nv_bfloat16 bb = __float2bfloat16_rn(v.y);
    __nv_bfloat16 c = __float2bfloat16_rn(v.z);
    __nv_bfloat16 d = __float2bfloat16_rn(v.w);
    __nv_bfloat162 hl; hl.x = a;  hl.y = bb;
    __nv_bfloat162 hh; hh.x = c;  hh.y = d;
    h0 = *(uint32_t*)&hl; h1 = *(uint32_t*)&hh;
    __nv_bfloat16 ma = __float2bfloat16_rn(v.x - __bfloat162float(a));
    __nv_bfloat16 mb = __float2bfloat16_rn(v.y - __bfloat162float(bb));
    __nv_bfloat16 mc = __float2bfloat16_rn(v.z - __bfloat162float(c));
    __nv_bfloat16 md = __float2bfloat16_rn(v.w - __bfloat162float(d));
    __nv_bfloat162 ml; ml.x = ma; ml.y = mb;
    __nv_bfloat162 mh; mh.x = mc; mh.y = md;
    q0 = *(uint32_t*)&ml; q1 = *(uint32_t*)&mh;
}

// ---------------------------------------------------------------------------
// mean + analytic trace: trace(cov) = (Σ||v||² - N||mean||²) / (N-1)
// ---------------------------------------------------------------------------
__global__ void mean_kernel(const float* __restrict__ feat,
                            const float* __restrict__ noise) {
    int b = blockIdx.x, c = threadIdx.x;
    const float* F  = feat  + (size_t)b * NPG * DIM + c;
    const float* Nz = noise + (size_t)b * NPG * DIM + c;
    float s = 0.f, q = 0.f;
    #pragma unroll 8
    for (int n = 0; n < NPG; ++n) {
        float v = F[(size_t)n * DIM] + NOISE_RATE * Nz[(size_t)n * DIM];
        s += v; q += v * v;
    }
    float m = s * (1.f / NPG);
    g_mean[b * DIM + c] = m;
    float t = q - (float)NPG * m * m;
    #pragma unroll
    for (int o = 16; o; o >>= 1) t += __shfl_xor_sync(0xffffffffu, t, o);
    __shared__ float sm[8];
    if ((c & 31) == 0) sm[c >> 5] = t;
    __syncthreads();
    if (c == 0) {
        float tot = 0.f;
        #pragma unroll
        for (int w = 0; w < 8; w++) tot += sm[w];
        g_norm[b] = tot * (1.f / (NPG - 1));
    }
}

// ---------------------------------------------------------------------------
// covariance (FFMA, proven) fused with normalize + Z0:
// A = cov/trace ; Z0 = 1.5I - 0.5*A
// ---------------------------------------------------------------------------
__global__ void __launch_bounds__(256) cov_kernel(const float* __restrict__ feat,
                                                  const float* __restrict__ noise) {
    int b  = blockIdx.z;
    int i0 = blockIdx.y * 128, j0 = blockIdx.x * 128;
    __shared__ float Ds[8][128];
    __shared__ float Es[8][128];
    int tid = threadIdx.x;
    int lk = tid >> 5, lq = (tid & 31) * 4;
    int tx = tid & 15, ty = tid >> 4;

    float acc[8][8];
    #pragma unroll
    for (int i = 0; i < 8; i++)
        #pragma unroll
        for (int j = 0; j < 8; j++) acc[i][j] = 0.f;

    float4 mi = *(const float4*)&g_mean[b * DIM + i0 + lq];
    float4 mj = *(const float4*)&g_mean[b * DIM + j0 + lq];
    const float* F  = feat  + (size_t)b * NPG * DIM;
    const float* Nz = noise + (size_t)b * NPG * DIM;

    for (int kt = 0; kt < NPG; kt += 8) {
        size_t row = (size_t)(kt + lk) * DIM;
        float4 f1 = *(const float4*)&F [row + i0 + lq];
        float4 n1 = *(const float4*)&Nz[row + i0 + lq];
        float4 f2 = *(const float4*)&F [row + j0 + lq];
        float4 n2 = *(const float4*)&Nz[row + j0 + lq];
        float4 di, dj;
        di.x = f1.x + NOISE_RATE * n1.x - mi.x;
        di.y = f1.y + NOISE_RATE * n1.y - mi.y;
        di.z = f1.z + NOISE_RATE * n1.z - mi.z;
        di.w = f1.w + NOISE_RATE * n1.w - mi.w;
        dj.x = f2.x + NOISE_RATE * n2.x - mj.x;
        dj.y = f2.y + NOISE_RATE * n2.y - mj.y;
        dj.z = f2.z + NOISE_RATE * n2.z - mj.z;
        dj.w = f2.w + NOISE_RATE * n2.w - mj.w;
        __syncthreads();
        *(float4*)&Ds[lk][lq] = di;
        *(float4*)&Es[lk][lq] = dj;
        __syncthreads();
        #pragma unroll
        for (int k = 0; k < 8; ++k) {
            float a[8], bb[8];
            *(float4*)(a)     = *(const float4*)&Ds[k][ty * 8];
            *(float4*)(a + 4) = *(const float4*)&Ds[k][ty * 8 + 4];
            *(float4*)(bb)     = *(const float4*)&Es[k][tx * 8];
            *(float4*)(bb + 4) = *(const float4*)&Es[k][tx * 8 + 4];
            #pragma unroll
            for (int i = 0; i < 8; i++)
                #pragma unroll
                for (int j = 0; j < 8; j++)
                    acc[i][j] += a[i] * bb[j];
        }
    }
    const float sc = 1.f / ((NPG - 1) * g_norm[b]);
    float* Av = g_A  + (size_t)b * DD;
    float* Zv = g_Z0 + (size_t)b * DD;
    #pragma unroll
    for (int i = 0; i < 8; i++) {
        int r = i0 + ty * 8 + i;
        #pragma unroll
        for (int j = 0; j < 8; j += 4) {
            int c = j0 + tx * 8 + j;
            float4 v, z;
            v.x = acc[i][j + 0] * sc;
            v.y = acc[i][j + 1] * sc;
            v.z = acc[i][j + 2] * sc;
            v.w = acc[i][j + 3] * sc;
            z.x = (r == c + 0 ? 1.5f : 0.f) - 0.5f * v.x;
            z.y = (r == c + 1 ? 1.5f : 0.f) - 0.5f * v.y;
            z.z = (r == c + 2 ? 1.5f : 0.f) - 0.5f * v.z;
            z.w = (r == c + 3 ? 1.5f : 0.f) - 0.5f * v.w;
            *(float4*)&Av[(size_t)r * DIM + c] = v;
            *(float4*)&Zv[(size_t)r * DIM + c] = z;
        }
    }
}

// ---------------------------------------------------------------------------
// batched 256x256x256 GEMM via bf16 mma.sync (2-term split, 3 products),
// ldmatrix feeding, CTA tile 128x64, warp tile 32x32, BK=32, 8 warps.
// Both operands read row-major (B symmetric => rows == B^T rows).
// mode 0: C = A@B.   mode 1: C = 1.5I - 0.5*(A@B)
// ---------------------------------------------------------------------------
#define BM 128
#define BN 64
#define BK 32
#define RSTRIDE 80                    // 32 bf16 = 64B data, padded to 80B (16B-aligned, conflict-free)
#define OFF_AH 0
#define OFF_AM (BM * RSTRIDE)         // 10240
#define OFF_BH (2 * BM * RSTRIDE)     // 20480
#define OFF_BM (2 * BM * RSTRIDE + BN * RSTRIDE)  // 25600
#define SMEM_GEMM (2 * BM * RSTRIDE + 2 * BN * RSTRIDE)  // 30720

__global__ void __launch_bounds__(256, 2) gemm_bf16(const float* __restrict__ Ag,
                                                    const float* __restrict__ Bg,
                                                    float* __restrict__ Cg, int mode) {
    __shared__ char smem[SMEM_GEMM];
    const uint32_t sb = smem_u32(smem);
    const int tid = threadIdx.x, lane = tid & 31, wid = tid >> 5;
    const int b = blockIdx.z;
    const int m0 = blockIdx.y * BM, n0 = blockIdx.x * BN;
    const int wm = (wid & 3) * 32, wn = (wid >> 2) * 32;
    const float* A  = Ag + (size_t)b * DD;
    const float* Bm = Bg + (size_t)b * DD;

    // staging: A 4 float4/thread, B 2 float4/thread
    const int srow = tid >> 3, skq = tid & 7;          // row-within-32-group, k-quad
    const float* gA = A  + (size_t)(m0 + srow) * DIM + skq * 4;
    const float* gB = Bm + (size_t)(n0 + srow) * DIM + skq * 4;

    // smem store addrs (bytes)
    const uint32_t stA = sb + (uint32_t)srow * RSTRIDE + skq * 8;
    const uint32_t stB = stA;  // same row/quad pattern, different tile offset

    // ldmatrix base addresses (per lane)
    // A tile mt (0..1): rows wm + mt*16 + (lane&15), k-seg (lane>>4)&1
    uint32_t aAd[2];
    #pragma unroll
    for (int mt = 0; mt < 2; mt++)
        aAd[mt] = sb + OFF_AH + (uint32_t)(wm + mt * 16 + (lane & 15)) * RSTRIDE
                + ((lane >> 4) & 1) * 16;
    // B pair p (0..1): rows wn + p*16 + (lane&7) + ((lane>>4)&1)*8, k-seg (lane>>3)&1
    uint32_t bAd[2];
    #pragma unroll
    for (int p = 0; p < 2; p++)
        bAd[p] = sb + OFF_BH + (uint32_t)(wn + p * 16 + (lane & 7) + ((lane >> 4) & 1) * 8) * RSTRIDE
               + ((lane >> 3) & 1) * 16;

    float acc[2][4][4];
    #pragma unroll
    for (int mt = 0; mt < 2; mt++)
        #pragma unroll
        for (int nt = 0; nt < 4; nt++)
            #pragma unroll
            for (int k = 0; k < 4; k++) acc[mt][nt][k] = 0.f;

    float4 pa[4], pb[2];
    #pragma unroll
    for (int p = 0; p < 4; p++) pa[p] = *(const float4*)(gA + (size_t)p * 32 * DIM);
    #pragma unroll
    for (int p = 0; p < 2; p++) pb[p] = *(const float4*)(gB + (size_t)p * 32 * DIM);

    for (int kc = 0; kc < 8; ++kc) {
        // split + STS
        #pragma unroll
        for (int p = 0; p < 4; p++) {
            uint32_t h0, h1, q0, q1;
            split4(pa[p], h0, h1, q0, q1);
            uint32_t ad = stA + p * 32 * RSTRIDE;
            *(uint2*)(size_t)(0) ;  // (placeholder removed below)
            // store via shared pointers
            *((uint2*)(smem + (ad - sb) + OFF_AH)) = make_uint2(h0, h1);
            *((uint2*)(smem + (ad - sb) + OFF_AM)) = make_uint2(q0, q1);
        }
        #pragma unroll
        for (int p = 0; p < 2; p++) {
            uint32_t h0, h1, q0, q1;
            split4(pb[p], h0, h1, q0, q1);
            uint32_t ad = stB + p * 32 * RSTRIDE;
            *((uint2*)(smem + (ad - sb) + OFF_BH)) = make_uint2(h0, h1);
            *((uint2*)(smem + (ad - sb) + OFF_BM)) = make_uint2(q0, q1);
        }
        __syncthreads();
        // prefetch next chunk
        if (kc < 7) {
            #pragma unroll
            for (int p = 0; p < 4; p++) pa[p] = *(const float4*)(gA + (size_t)p * 32 * DIM + (kc + 1) * 32);
            #pragma unroll
            for (int p = 0; p < 2; p++) pb[p] = *(const float4*)(gB + (size_t)p * 32 * DIM + (kc + 1) * 32);
        }
        #pragma unroll
        for (int kk = 0; kk < 2; kk++) {
            uint32_t ah[2][4], am[2][4];
            #pragma unroll
            for (int mt = 0; mt < 2; mt++) {
                ldm4(ah[mt], aAd[mt] + kk * 32);
                ldm4(am[mt], aAd[mt] + kk * 32 + (OFF_AM - OFF_AH));
            }
            // bs = 0 (B.h): products hh and mh
            {
                uint32_t bb[2][4];
                #pragma unroll
                for (int p = 0; p < 2; p++) ldm4(bb[p], bAd[p] + kk * 32);
                #pragma unroll
                for (int mt = 0; mt < 2; mt++)
                    #pragma unroll
                    for (int nt = 0; nt < 4; nt++) {
                        mma16816(acc[mt][nt], ah[mt], &bb[nt >> 1][(nt & 1) * 2]);
                        mma16816(acc[mt][nt], am[mt], &bb[nt >> 1][(nt & 1) * 2]);
                    }
            }
            // bs = 1 (B.m): product hm
            {
                uint32_t bb[2][4];
                #pragma unroll
                for (int p = 0; p < 2; p++) ldm4(bb[p], bAd[p] + kk * 32 + (OFF_BM - OFF_BH));
                #pragma unroll
                for (int mt = 0; mt < 2; mt++)
                    #pragma unroll
                    for (int nt = 0; nt < 4; nt++)
                        mma16816(acc[mt][nt], ah[mt], &bb[nt >> 1][(nt & 1) * 2]);
            }
        }
        __syncthreads();
    }

    // epilogue
    float* C = Cg + (size_t)b * DD;
    int rr = m0 + wm + (lane >> 2);
    int cc = n0 + wn + (lane & 3) * 2;
    #pragma unroll
    for (int mt = 0; mt < 2; mt++) {
        #pragma unroll
        for (int nt = 0; nt < 4; nt++) {
            int r = rr + mt * 16, c = cc + nt * 8;
            float v0 = acc[mt][nt][0], v1 = acc[mt][nt][1];
            float v2 = acc[mt][nt][2], v3 = acc[mt][nt][3];
            if (mode == 1) {
                v0 = (r == c     ? 1.5f : 0.f) - 0.5f * v0;
                v1 = (r == c + 1 ? 1.5f : 0.f) - 0.5f * v1;
                v2 = (r + 8 == c     ? 1.5f : 0.f) - 0.5f * v2;
                v3 = (r + 8 == c + 1 ? 1.5f : 0.f) - 0.5f * v3;
            }
            *(float2*)&C[(size_t)r * DIM + c]       = make_float2(v0, v1);
            *(float2*)&C[(size_t)(r + 8) * DIM + c] = make_float2(v2, v3);
        }
    }
}

// ---------------------------------------------------------------------------
// out[b] = scale * (M[b] @ vin[b]).  scale = sqrt(norm[b]) if useScale.
// ---------------------------------------------------------------------------
__global__ void matvec_kernel(const float* __restrict__ M,
                              const float* __restrict__ vin,
                              float* __restrict__ outp, int useScale) {
    int b = blockIdx.x;
    __shared__ float vs[DIM];
    int tid = threadIdx.x;
    vs[tid] = vin[b * DIM + tid];
    __syncthreads();
    int warp = tid >> 5, lane = tid & 31;
    const float* Mb = M + (size_t)b * DD;
    float scale = useScale ? sqrtf(g_norm[b]) : 1.f;
    for (int r = warp; r < DIM; r += 8) {
        float s = 0.f;
        #pragma unroll
        for (int c = lane; c < DIM; c += 32) s += Mb[(size_t)r * DIM + c] * vs[c];
        #pragma unroll
        for (int o = 16; o; o >>= 1) s += __shfl_xor_sync(0xffffffffu, s, o);
        if (lane == 0) outp[b * DIM + r] = s * scale;
    }
}

// ---------------------------------------------------------------------------
extern "C" void kernel_launch(void* const* d_in, const int* in_sizes, int n_in,
                              void* d_out, int out_size) {
    const float* feat  = (const float*)d_in[0];
    const float* noise = (const float*)d_in[1];
    float* out = (float*)d_out;

    float *A, *Y0, *Y1, *Z0, *Z1, *T, *Mean, *Vv;
    cudaGetSymbolAddress((void**)&A,    g_A);
    cudaGetSymbolAddress((void**)&Y0,   g_Y0);
    cudaGetSymbolAddress((void**)&Y1,   g_Y1);
    cudaGetSymbolAddress((void**)&Z0,   g_Z0);
    cudaGetSymbolAddress((void**)&Z1,   g_Z1);
    cudaGetSymbolAddress((void**)&T,    g_T);
    cudaGetSymbolAddress((void**)&Mean, g_mean);
    cudaGetSymbolAddress((void**)&Vv,   g_v);

    mean_kernel<<<NB, DIM>>>(feat, noise);            // mean + analytic trace
    cov_kernel<<<dim3(2, 2, NB), 256>>>(feat, noise); // A = cov/tr, Z0 = 1.5I-0.5A

    dim3 gg(DIM / BN, DIM / BM, NB);                  // (4, 2, 128)
    gemm_bf16<<<gg, 256>>>(A, Z0, Y0, 0);             // Y = A @ Z0

    float* Yc[2] = {Y0, Y1};
    float* Zc[2] = {Z0, Z1};
    int cur = 0;
    for (int it = 0; it < 3; ++it) {                  // ITERN=5 -> 3 middle iters
        gemm_bf16<<<gg, 256>>>(Zc[cur], Yc[cur], T, 1);      // T = 1.5I-0.5*Z@Y
        gemm_bf16<<<gg, 256>>>(Yc[cur], T, Yc[1 - cur], 0);  // Y' = Y@T
        gemm_bf16<<<gg, 256>>>(T, Zc[cur], Zc[1 - cur], 0);  // Z' = T@Z
        cur ^= 1;
    }
    gemm_bf16<<<gg, 256>>>(Zc[cur], Yc[cur], T, 1);   // S = 1.5I-0.5*Z@Y
    matvec_kernel<<<NB, DIM>>>(T, Mean, Vv, 0);       // v = S @ mean
    matvec_kernel<<<NB, DIM>>>(Yc[cur], Vv, out, 1);  // out = sqrt(tr)*Y@v
}

// round 6
// speedup vs baseline: 3.0510x; 1.2270x over previous
#include <cuda_runtime.h>
#include <cuda_bf16.h>
#include <math.h>
#include <stdint.h>

// Problem constants: feat [65536, 256], n_per_graph = 512 -> B = 128, d = 256.
#define NB   128
#define NPG  512
#define DIM  256
#define DD   (DIM*DIM)
#define BD   (NB*DD)
#define NOISE_RATE 0.01f

// Scratch (allocation-free rule: device globals)
__device__ float g_A[BD];      // A = cov/trace (fp32), preserved
__device__ float g_DTh[BD];    // reinterpreted as bf16 [B][DIM][NPG]: diff^T hi
__device__ float g_DTm[BD];    // reinterpreted as bf16 [B][DIM][NPG]: diff^T lo
__device__ float g_X2[BD];     // M^2 scratch
__device__ float g_M0[BD];     // M ping
__device__ float g_M1[BD];     // M pong
__device__ float g_mean[NB*DIM];
__device__ float g_v[NB*DIM];
__device__ float g_norm[NB];

// ---------------------------------------------------------------------------
// helpers
// ---------------------------------------------------------------------------
__device__ __forceinline__ uint32_t smem_u32(const void* p) {
    uint32_t a;
    asm("{ .reg .u64 t; cvta.to.shared.u64 t, %1; cvt.u32.u64 %0, t; }" : "=r"(a) : "l"(p));
    return a;
}
__device__ __forceinline__ void ldm4(uint32_t* r, uint32_t a) {
    asm volatile("ldmatrix.sync.aligned.m8n8.x4.shared.b16 {%0,%1,%2,%3}, [%4];"
                 : "=r"(r[0]), "=r"(r[1]), "=r"(r[2]), "=r"(r[3]) : "r"(a));
}
__device__ __forceinline__ void mma16816(float* c, const uint32_t* a, const uint32_t* bq) {
    asm volatile("mma.sync.aligned.m16n8k16.row.col.f32.bf16.bf16.f32 "
                 "{%0,%1,%2,%3}, {%4,%5,%6,%7}, {%8,%9}, {%0,%1,%2,%3};"
                 : "+f"(c[0]), "+f"(c[1]), "+f"(c[2]), "+f"(c[3])
                 : "r"(a[0]), "r"(a[1]), "r"(a[2]), "r"(a[3]), "r"(bq[0]), "r"(bq[1]));
}
// bf16 2-term split of 4 floats -> packed h (2x u32) and m (2x u32)
__device__ __forceinline__ void split4(float4 v, uint32_t& h0, uint32_t& h1,
                                       uint32_t& q0, uint32_t& q1) {
    __nv_bfloat16 a = __float2bfloat16_rn(v.x);
    __nv_bfloat16 bb = __float2bfloat16_rn(v.y);
    __nv_bfloat16 c = __float2bfloat16_rn(v.z);
    __nv_bfloat16 d = __float2bfloat16_rn(v.w);
    __nv_bfloat162 hl; hl.x = a;  hl.y = bb;
    __nv_bfloat162 hh; hh.x = c;  hh.y = d;
    h0 = *(uint32_t*)&hl; h1 = *(uint32_t*)&hh;
    __nv_bfloat16 ma = __float2bfloat16_rn(v.x - __bfloat162float(a));
    __nv_bfloat16 mb = __float2bfloat16_rn(v.y - __bfloat162float(bb));
    __nv_bfloat16 mc = __float2bfloat16_rn(v.z - __bfloat162float(c));
    __nv_bfloat16 md = __float2bfloat16_rn(v.w - __bfloat162float(d));
    __nv_bfloat162 ml; ml.x = ma; ml.y = mb;
    __nv_bfloat162 mh; mh.x = mc; mh.y = md;
    q0 = *(uint32_t*)&ml; q1 = *(uint32_t*)&mh;
}

// ---------------------------------------------------------------------------
// mean + analytic trace: trace(cov) = (Σ||v||² - N||mean||²) / (N-1)
// ---------------------------------------------------------------------------
__global__ void mean_kernel(const float* __restrict__ feat,
                            const float* __restrict__ noise) {
    int b = blockIdx.x, c = threadIdx.x;
    const float* F  = feat  + (size_t)b * NPG * DIM + c;
    const float* Nz = noise + (size_t)b * NPG * DIM + c;
    float s = 0.f, q = 0.f;
    #pragma unroll 8
    for (int n = 0; n < NPG; ++n) {
        float v = F[(size_t)n * DIM] + NOISE_RATE * Nz[(size_t)n * DIM];
        s += v; q += v * v;
    }
    float m = s * (1.f / NPG);
    g_mean[b * DIM + c] = m;
    float t = q - (float)NPG * m * m;
    #pragma unroll
    for (int o = 16; o; o >>= 1) t += __shfl_xor_sync(0xffffffffu, t, o);
    __shared__ float sm[8];
    if ((c & 31) == 0) sm[c >> 5] = t;
    __syncthreads();
    if (c == 0) {
        float tot = 0.f;
        #pragma unroll
        for (int w = 0; w < 8; w++) tot += sm[w];
        g_norm[b] = tot * (1.f / (NPG - 1));
    }
}

// ---------------------------------------------------------------------------
// prep: diff^T split to bf16 (h, m), transposed to [b][dim][node].
// 32x32 tiles through smem.
// ---------------------------------------------------------------------------
__global__ void prep_kernel(const float* __restrict__ feat,
                            const float* __restrict__ noise,
                            __nv_bfloat16* __restrict__ DTh,
                            __nv_bfloat16* __restrict__ DTm) {
    int b = blockIdx.z;
    int n0 = blockIdx.x * 32, d0 = blockIdx.y * 32;
    __shared__ float t[32][33];
    __shared__ float mn[32];
    int tid = threadIdx.x;
    if (tid < 32) mn[tid] = g_mean[b * DIM + d0 + tid];
    __syncthreads();
    {
        int n = tid >> 3, dq = (tid & 7) * 4;
        size_t off = ((size_t)(b * NPG + n0 + n)) * DIM + d0 + dq;
        float4 f = *(const float4*)&feat[off];
        float4 z = *(const float4*)&noise[off];
        t[n][dq + 0] = f.x + NOISE_RATE * z.x - mn[dq + 0];
        t[n][dq + 1] = f.y + NOISE_RATE * z.y - mn[dq + 1];
        t[n][dq + 2] = f.z + NOISE_RATE * z.z - mn[dq + 2];
        t[n][dq + 3] = f.w + NOISE_RATE * z.w - mn[dq + 3];
    }
    __syncthreads();
    {
        int d = tid >> 3, nq = (tid & 7) * 4;
        float4 v = make_float4(t[nq + 0][d], t[nq + 1][d], t[nq + 2][d], t[nq + 3][d]);
        uint32_t h0, h1, m0, m1;
        split4(v, h0, h1, m0, m1);
        size_t off = ((size_t)(b * DIM + d0 + d)) * NPG + n0 + nq;
        *(uint2*)&DTh[off] = make_uint2(h0, h1);
        *(uint2*)&DTm[off] = make_uint2(m0, m1);
    }
}

// ---------------------------------------------------------------------------
// shared GEMM geometry (proven round-5 inner loop)
// ---------------------------------------------------------------------------
#define BM 128
#define BN 64
#define RSTRIDE 80                    // 32 bf16 = 64B data, padded to 80B
#define OFF_AH 0
#define OFF_AM (BM * RSTRIDE)         // 10240
#define OFF_BH (2 * BM * RSTRIDE)     // 20480
#define OFF_BM (2 * BM * RSTRIDE + BN * RSTRIDE)  // 25600
#define SMEM_GEMM (2 * BM * RSTRIDE + 2 * BN * RSTRIDE)  // 30720

// Per-warp ldmatrix addresses + mainloop body as macros to share between kernels
#define GEMM_FRAG_SETUP()                                                         \
    uint32_t aAd[2];                                                              \
    _Pragma("unroll")                                                             \
    for (int mt = 0; mt < 2; mt++)                                                \
        aAd[mt] = sb + OFF_AH + (uint32_t)(wm + mt * 16 + (lane & 15)) * RSTRIDE  \
                + ((lane >> 4) & 1) * 16;                                         \
    uint32_t bAd[2];                                                              \
    _Pragma("unroll")                                                             \
    for (int p = 0; p < 2; p++)                                                   \
        bAd[p] = sb + OFF_BH + (uint32_t)(wn + p * 16 + (lane & 7) + ((lane >> 4) & 1) * 8) * RSTRIDE \
               + ((lane >> 3) & 1) * 16;

#define GEMM_MAINLOOP_CHUNK()                                                     \
    _Pragma("unroll")                                                             \
    for (int kk = 0; kk < 2; kk++) {                                              \
        uint32_t ah[2][4], am[2][4];                                              \
        _Pragma("unroll")                                                         \
        for (int mt = 0; mt < 2; mt++) {                                          \
            ldm4(ah[mt], aAd[mt] + kk * 32);                                      \
            ldm4(am[mt], aAd[mt] + kk * 32 + (OFF_AM - OFF_AH));                  \
        }                                                                         \
        {                                                                         \
            uint32_t bb[2][4];                                                    \
            _Pragma("unroll")                                                     \
            for (int p = 0; p < 2; p++) ldm4(bb[p], bAd[p] + kk * 32);            \
            _Pragma("unroll")                                                     \
            for (int mt = 0; mt < 2; mt++)                                        \
                _Pragma("unroll")                                                 \
                for (int nt = 0; nt < 4; nt++) {                                  \
                    mma16816(acc[mt][nt], ah[mt], &bb[nt >> 1][(nt & 1) * 2]);    \
                    mma16816(acc[mt][nt], am[mt], &bb[nt >> 1][(nt & 1) * 2]);    \
                }                                                                 \
        }                                                                         \
        {                                                                         \
            uint32_t bb[2][4];                                                    \
            _Pragma("unroll")                                                     \
            for (int p = 0; p < 2; p++) ldm4(bb[p], bAd[p] + kk * 32 + (OFF_BM - OFF_BH)); \
            _Pragma("unroll")                                                     \
            for (int mt = 0; mt < 2; mt++)                                        \
                _Pragma("unroll")                                                 \
                for (int nt = 0; nt < 4; nt++)                                    \
                    mma16816(acc[mt][nt], ah[mt], &bb[nt >> 1][(nt & 1) * 2]);    \
        }                                                                         \
    }

// ---------------------------------------------------------------------------
// batched 256x256x256 GEMM via bf16 split (fp32 operands, split on load).
// mode 0: C = A@B
// mode 1: C = 2.25*P - 1.5*Q + 0.25*(A@B)   (f-map epilogue; P=M, Q=M^2)
// ---------------------------------------------------------------------------
__global__ void __launch_bounds__(256, 2) gemm_bf16(const float* __restrict__ Ag,
                                                    const float* __restrict__ Bg,
                                                    float* __restrict__ Cg,
                                                    const float* __restrict__ Pg,
                                                    const float* __restrict__ Qg,
                                                    int mode) {
    __shared__ char smem[SMEM_GEMM];
    const uint32_t sb = smem_u32(smem);
    const int tid = threadIdx.x, lane = tid & 31, wid = tid >> 5;
    const int b = blockIdx.z;
    const int m0 = blockIdx.y * BM, n0 = blockIdx.x * BN;
    const int wm = (wid & 3) * 32, wn = (wid >> 2) * 32;
    const float* A  = Ag + (size_t)b * DD;
    const float* Bm = Bg + (size_t)b * DD;

    const int srow = tid >> 3, skq = tid & 7;
    const float* gA = A  + (size_t)(m0 + srow) * DIM + skq * 4;
    const float* gB = Bm + (size_t)(n0 + srow) * DIM + skq * 4;
    const uint32_t stOff = (uint32_t)srow * RSTRIDE + skq * 8;

    GEMM_FRAG_SETUP();

    float acc[2][4][4];
    #pragma unroll
    for (int mt = 0; mt < 2; mt++)
        #pragma unroll
        for (int nt = 0; nt < 4; nt++)
            #pragma unroll
            for (int k = 0; k < 4; k++) acc[mt][nt][k] = 0.f;

    float4 pa[4], pb[2];
    #pragma unroll
    for (int p = 0; p < 4; p++) pa[p] = *(const float4*)(gA + (size_t)p * 32 * DIM);
    #pragma unroll
    for (int p = 0; p < 2; p++) pb[p] = *(const float4*)(gB + (size_t)p * 32 * DIM);

    for (int kc = 0; kc < 8; ++kc) {
        #pragma unroll
        for (int p = 0; p < 4; p++) {
            uint32_t h0, h1, q0, q1;
            split4(pa[p], h0, h1, q0, q1);
            uint32_t ad = stOff + p * 32 * RSTRIDE;
            *((uint2*)(smem + ad + OFF_AH)) = make_uint2(h0, h1);
            *((uint2*)(smem + ad + OFF_AM)) = make_uint2(q0, q1);
        }
        #pragma unroll
        for (int p = 0; p < 2; p++) {
            uint32_t h0, h1, q0, q1;
            split4(pb[p], h0, h1, q0, q1);
            uint32_t ad = stOff + p * 32 * RSTRIDE;
            *((uint2*)(smem + ad + OFF_BH)) = make_uint2(h0, h1);
            *((uint2*)(smem + ad + OFF_BM)) = make_uint2(q0, q1);
        }
        __syncthreads();
        if (kc < 7) {
            #pragma unroll
            for (int p = 0; p < 4; p++) pa[p] = *(const float4*)(gA + (size_t)p * 32 * DIM + (kc + 1) * 32);
            #pragma unroll
            for (int p = 0; p < 2; p++) pb[p] = *(const float4*)(gB + (size_t)p * 32 * DIM + (kc + 1) * 32);
        }
        GEMM_MAINLOOP_CHUNK();
        __syncthreads();
    }

    float* C = Cg + (size_t)b * DD;
    const float* P = Pg + (size_t)b * DD;
    const float* Q = Qg + (size_t)b * DD;
    int rr = m0 + wm + (lane >> 2);
    int cc = n0 + wn + (lane & 3) * 2;
    #pragma unroll
    for (int mt = 0; mt < 2; mt++) {
        #pragma unroll
        for (int nt = 0; nt < 4; nt++) {
            int r = rr + mt * 16, c = cc + nt * 8;
            float v0 = acc[mt][nt][0], v1 = acc[mt][nt][1];
            float v2 = acc[mt][nt][2], v3 = acc[mt][nt][3];
            if (mode == 1) {
                float2 p0 = *(const float2*)&P[(size_t)r * DIM + c];
                float2 p1 = *(const float2*)&P[(size_t)(r + 8) * DIM + c];
                float2 q0 = *(const float2*)&Q[(size_t)r * DIM + c];
                float2 q1 = *(const float2*)&Q[(size_t)(r + 8) * DIM + c];
                v0 = 2.25f * p0.x - 1.5f * q0.x + 0.25f * v0;
                v1 = 2.25f * p0.y - 1.5f * q0.y + 0.25f * v1;
                v2 = 2.25f * p1.x - 1.5f * q1.x + 0.25f * v2;
                v3 = 2.25f * p1.y - 1.5f * q1.y + 0.25f * v3;
            }
            *(float2*)&C[(size_t)r * DIM + c]       = make_float2(v0, v1);
            *(float2*)&C[(size_t)(r + 8) * DIM + c] = make_float2(v2, v3);
        }
    }
}

// ---------------------------------------------------------------------------
// covariance GEMM: A = (diff^T @ diff) / ((N-1)*trace), from pre-split bf16
// DTh/DTm [b][dim][node].  Same mainloop; K = 512 (16 chunks).
// ---------------------------------------------------------------------------
__global__ void __launch_bounds__(256, 2) cov_mma(const __nv_bfloat16* __restrict__ DTh,
                                                  const __nv_bfloat16* __restrict__ DTm,
                                                  float* __restrict__ Cg) {
    __shared__ char smem[SMEM_GEMM];
    const uint32_t sb = smem_u32(smem);
    const int tid = threadIdx.x, lane = tid & 31, wid = tid >> 5;
    const int b = blockIdx.z;
    const int m0 = blockIdx.y * BM, n0 = blockIdx.x * BN;
    const int wm = (wid & 3) * 32, wn = (wid >> 2) * 32;

    // loaders: slot = (row, quad) ; A: 128 rows x 4 quads (2 passes), B: 64 x 4 (1 pass)
    const int lrow = tid >> 2, lq = tid & 3;
    const __nv_bfloat16* baseH = DTh + (size_t)b * DIM * NPG;
    const __nv_bfloat16* baseM = DTm + (size_t)b * DIM * NPG;

    GEMM_FRAG_SETUP();

    float acc[2][4][4];
    #pragma unroll
    for (int mt = 0; mt < 2; mt++)
        #pragma unroll
        for (int nt = 0; nt < 4; nt++)
            #pragma unroll
            for (int k = 0; k < 4; k++) acc[mt][nt][k] = 0.f;

    uint4 pAh[2], pAm[2], pBh, pBm;
    {
        size_t a0 = (size_t)(m0 + lrow) * NPG + lq * 8;
        size_t a1 = (size_t)(m0 + 64 + lrow) * NPG + lq * 8;
        size_t b0 = (size_t)(n0 + lrow) * NPG + lq * 8;
        pAh[0] = *(const uint4*)(baseH + a0); pAm[0] = *(const uint4*)(baseM + a0);
        pAh[1] = *(const uint4*)(baseH + a1); pAm[1] = *(const uint4*)(baseM + a1);
        pBh    = *(const uint4*)(baseH + b0); pBm    = *(const uint4*)(baseM + b0);
    }

    for (int kc = 0; kc < 16; ++kc) {
        {
            uint32_t ad0 = (uint32_t)lrow * RSTRIDE + lq * 16;
            uint32_t ad1 = (uint32_t)(64 + lrow) * RSTRIDE + lq * 16;
            *((uint4*)(smem + ad0 + OFF_AH)) = pAh[0];
            *((uint4*)(smem + ad0 + OFF_AM)) = pAm[0];
            *((uint4*)(smem + ad1 + OFF_AH)) = pAh[1];
            *((uint4*)(smem + ad1 + OFF_AM)) = pAm[1];
            *((uint4*)(smem + ad0 + OFF_BH)) = pBh;
            *((uint4*)(smem + ad0 + OFF_BM)) = pBm;
        }
        __syncthreads();
        if (kc < 15) {
            size_t ko = (size_t)(kc + 1) * 32 + lq * 8;
            size_t a0 = (size_t)(m0 + lrow) * NPG + ko;
            size_t a1 = (size_t)(m0 + 64 + lrow) * NPG + ko;
            size_t b0 = (size_t)(n0 + lrow) * NPG + ko;
            pAh[0] = *(const uint4*)(baseH + a0); pAm[0] = *(const uint4*)(baseM + a0);
            pAh[1] = *(const uint4*)(baseH + a1); pAm[1] = *(const uint4*)(baseM + a1);
            pBh    = *(const uint4*)(baseH + b0); pBm    = *(const uint4*)(baseM + b0);
        }
        GEMM_MAINLOOP_CHUNK();
        __syncthreads();
    }

    float* C = Cg + (size_t)b * DD;
    const float sc = 1.f / ((NPG - 1) * g_norm[b]);
    int rr = m0 + wm + (lane >> 2);
    int cc = n0 + wn + (lane & 3) * 2;
    #pragma unroll
    for (int mt = 0; mt < 2; mt++) {
        #pragma unroll
        for (int nt = 0; nt < 4; nt++) {
            int r = rr + mt * 16, c = cc + nt * 8;
            *(float2*)&C[(size_t)r * DIM + c] =
                make_float2(acc[mt][nt][0] * sc, acc[mt][nt][1] * sc);
            *(float2*)&C[(size_t)(r + 8) * DIM + c] =
                make_float2(acc[mt][nt][2] * sc, acc[mt][nt][3] * sc);
        }
    }
}

// ---------------------------------------------------------------------------
// out[b] = scale * (alpha*vin[b] + beta*(M[b] @ vin[b])); scale=sqrt(norm) opt.
// In-place safe (vin cached to smem before writes).
// ---------------------------------------------------------------------------
__global__ void matvec_kernel(const float* __restrict__ M,
                              const float* __restrict__ vin,
                              float* __restrict__ outp,
                              float alpha, float beta, int useScale) {
    int b = blockIdx.x;
    __shared__ float vs[DIM];
    int tid = threadIdx.x;
    vs[tid] = vin[b * DIM + tid];
    __syncthreads();
    int warp = tid >> 5, lane = tid & 31;
    const float* Mb = M + (size_t)b * DD;
    float scale = useScale ? sqrtf(g_norm[b]) : 1.f;
    for (int r = warp; r < DIM; r += 8) {
        float s = 0.f;
        #pragma unroll
        for (int c = lane; c < DIM; c += 32) s += Mb[(size_t)r * DIM + c] * vs[c];
        #pragma unroll
        for (int o = 16; o; o >>= 1) s += __shfl_xor_sync(0xffffffffu, s, o);
        if (lane == 0) outp[b * DIM + r] = scale * (alpha * vs[r] + beta * s);
    }
}

// ---------------------------------------------------------------------------
extern "C" void kernel_launch(void* const* d_in, const int* in_sizes, int n_in,
                              void* d_out, int out_size) {
    const float* feat  = (const float*)d_in[0];
    const float* noise = (const float*)d_in[1];
    float* out = (float*)d_out;

    float *A, *DTh, *DTm, *X2, *M0, *M1, *Mean, *Vv;
    cudaGetSymbolAddress((void**)&A,    g_A);
    cudaGetSymbolAddress((void**)&DTh,  g_DTh);
    cudaGetSymbolAddress((void**)&DTm,  g_DTm);
    cudaGetSymbolAddress((void**)&X2,   g_X2);
    cudaGetSymbolAddress((void**)&M0,   g_M0);
    cudaGetSymbolAddress((void**)&M1,   g_M1);
    cudaGetSymbolAddress((void**)&Mean, g_mean);
    cudaGetSymbolAddress((void**)&Vv,   g_v);

    mean_kernel<<<NB, DIM>>>(feat, noise);
    prep_kernel<<<dim3(NPG / 32, DIM / 32, NB), 256>>>(feat, noise,
        (__nv_bfloat16*)DTh, (__nv_bfloat16*)DTm);
    cov_mma<<<dim3(DIM / BN, DIM / BM, NB), 256>>>(
        (const __nv_bfloat16*)DTh, (const __nv_bfloat16*)DTm, A);

    // v1 = 1.5*mean - 0.5*A@mean
    matvec_kernel<<<NB, DIM>>>(A, Mean, Vv, 1.5f, -0.5f, 0);

    // 4 applications of f(M) = 2.25M - 1.5M^2 + 0.25M^3 ; M_0 = A
    dim3 gg(DIM / BN, DIM / BM, NB);
    float* Mcur = A;
    float* Mbuf[2] = {M0, M1};
    for (int k = 0; k < 4; ++k) {
        float* Mnext = Mbuf[k & 1];
        gemm_bf16<<<gg, 256>>>(Mcur, Mcur, X2, A, A, 0);            // X2 = M@M
        gemm_bf16<<<gg, 256>>>(X2, Mcur, Mnext, Mcur, X2, 1);       // M' = f(M)
        // v <- 1.5v - 0.5*M'v   (k<3: v_{k+2};  k=3: u = T(M_4) v_4)
        matvec_kernel<<<NB, DIM>>>(Mnext, Vv, Vv, 1.5f, -0.5f, 0);
        Mcur = Mnext;
    }
    // out = sqrt(trace) * A @ u
    matvec_kernel<<<NB, DIM>>>(A, Vv, out, 0.f, 1.f, 1);
}

// round 8
// speedup vs baseline: 3.2355x; 1.0605x over previous
#include <cuda_runtime.h>
#include <cuda_bf16.h>
#include <math.h>
#include <stdint.h>

// Problem constants: feat [65536, 256], n_per_graph = 512 -> B = 128, d = 256.
#define NB   128
#define NPG  512
#define DIM  256
#define DD   (DIM*DIM)
#define BD   (NB*DD)
#define NOISE_RATE 0.01f

// Scratch (allocation-free rule: device globals)
__device__ float g_A[BD];      // A = cov/trace (fp32), preserved
__device__ float g_DTh[BD];    // reinterpreted as bf16 [B][DIM][NPG]: diff^T hi
__device__ float g_DTm[BD];    // reinterpreted as bf16 [B][DIM][NPG]: diff^T lo
__device__ float g_X2[BD];     // M^2 scratch
__device__ float g_M0[BD];     // M ping
__device__ float g_M1[BD];     // M pong
__device__ float g_mean[NB*DIM];
__device__ float g_va[NB*DIM];
__device__ float g_vb[NB*DIM];
__device__ float g_norm[NB];
__device__ float g_psum[NB*4*DIM];
__device__ float g_psq[NB*4*DIM];

// ---------------------------------------------------------------------------
// helpers
// ---------------------------------------------------------------------------
__device__ __forceinline__ uint32_t smem_u32(const void* p) {
    uint32_t a;
    asm("{ .reg .u64 t; cvta.to.shared.u64 t, %1; cvt.u32.u64 %0, t; }" : "=r"(a) : "l"(p));
    return a;
}
__device__ __forceinline__ void ldm4(uint32_t* r, uint32_t a) {
    asm volatile("ldmatrix.sync.aligned.m8n8.x4.shared.b16 {%0,%1,%2,%3}, [%4];"
                 : "=r"(r[0]), "=r"(r[1]), "=r"(r[2]), "=r"(r[3]) : "r"(a));
}
__device__ __forceinline__ void mma16816(float* c, const uint32_t* a, const uint32_t* bq) {
    asm volatile("mma.sync.aligned.m16n8k16.row.col.f32.bf16.bf16.f32 "
                 "{%0,%1,%2,%3}, {%4,%5,%6,%7}, {%8,%9}, {%0,%1,%2,%3};"
                 : "+f"(c[0]), "+f"(c[1]), "+f"(c[2]), "+f"(c[3])
                 : "r"(a[0]), "r"(a[1]), "r"(a[2]), "r"(a[3]), "r"(bq[0]), "r"(bq[1]));
}
// bf16 2-term split of 4 floats -> packed h (2x u32) and m (2x u32)
__device__ __forceinline__ void split4(float4 v, uint32_t& h0, uint32_t& h1,
                                       uint32_t& q0, uint32_t& q1) {
    __nv_bfloat16 a = __float2bfloat16_rn(v.x);
    __nv_bfloat16 bb = __float2bfloat16_rn(v.y);
    __nv_bfloat16 c = __float2bfloat16_rn(v.z);
    __nv_bfloat16 d = __float2bfloat16_rn(v.w);
    __nv_bfloat162 hl; hl.x = a;  hl.y = bb;
    __nv_bfloat162 hh; hh.x = c;  hh.y = d;
    h0 = *(uint32_t*)&hl; h1 = *(uint32_t*)&hh;
    __nv_bfloat16 ma = __float2bfloat16_rn(v.x - __bfloat162float(a));
    __nv_bfloat16 mb = __float2bfloat16_rn(v.y - __bfloat162float(bb));
    __nv_bfloat16 mc = __float2bfloat16_rn(v.z - __bfloat162float(c));
    __nv_bfloat16 md = __float2bfloat16_rn(v.w - __bfloat162float(d));
    __nv_bfloat162 ml; ml.x = ma; ml.y = mb;
    __nv_bfloat162 mh; mh.x = mc; mh.y = md;
    q0 = *(uint32_t*)&ml; q1 = *(uint32_t*)&mh;
}

// ---------------------------------------------------------------------------
// mean stage 1: grid (4, NB), block 256: partial sum + sumsq over 128 nodes
// ---------------------------------------------------------------------------
__global__ void mean_part(const float* __restrict__ feat,
                          const float* __restrict__ noise) {
    int b = blockIdx.y, p = blockIdx.x, c = threadIdx.x;
    const float* F  = feat  + ((size_t)b * NPG + p * 128) * DIM + c;
    const float* Nz = noise + ((size_t)b * NPG + p * 128) * DIM + c;
    float s = 0.f, q = 0.f;
    #pragma unroll 8
    for (int n = 0; n < 128; ++n) {
        float v = F[(size_t)n * DIM] + NOISE_RATE * Nz[(size_t)n * DIM];
        s += v; q += v * v;
    }
    g_psum[(b * 4 + p) * DIM + c] = s;
    g_psq [(b * 4 + p) * DIM + c] = q;
}

// mean stage 2: grid NB, block 256: finalize mean + trace
__global__ void mean_final() {
    int b = blockIdx.x, c = threadIdx.x;
    float s = 0.f, q = 0.f;
    #pragma unroll
    for (int p = 0; p < 4; ++p) {
        s += g_psum[(b * 4 + p) * DIM + c];
        q += g_psq [(b * 4 + p) * DIM + c];
    }
    float m = s * (1.f / NPG);
    g_mean[b * DIM + c] = m;
    float t = q - (float)NPG * m * m;
    #pragma unroll
    for (int o = 16; o; o >>= 1) t += __shfl_xor_sync(0xffffffffu, t, o);
    __shared__ float sm[8];
    if ((c & 31) == 0) sm[c >> 5] = t;
    __syncthreads();
    if (c == 0) {
        float tot = 0.f;
        #pragma unroll
        for (int w = 0; w < 8; w++) tot += sm[w];
        g_norm[b] = tot * (1.f / (NPG - 1));
    }
}

// ---------------------------------------------------------------------------
// prep: diff^T split to bf16 (h, m), transposed to [b][dim][node].
// ---------------------------------------------------------------------------
__global__ void prep_kernel(const float* __restrict__ feat,
                            const float* __restrict__ noise,
                            __nv_bfloat16* __restrict__ DTh,
                            __nv_bfloat16* __restrict__ DTm) {
    int b = blockIdx.z;
    int n0 = blockIdx.x * 32, d0 = blockIdx.y * 32;
    __shared__ float t[32][33];
    __shared__ float mn[32];
    int tid = threadIdx.x;
    if (tid < 32) mn[tid] = g_mean[b * DIM + d0 + tid];
    __syncthreads();
    {
        int n = tid >> 3, dq = (tid & 7) * 4;
        size_t off = ((size_t)(b * NPG + n0 + n)) * DIM + d0 + dq;
        float4 f = *(const float4*)&feat[off];
        float4 z = *(const float4*)&noise[off];
        t[n][dq + 0] = f.x + NOISE_RATE * z.x - mn[dq + 0];
        t[n][dq + 1] = f.y + NOISE_RATE * z.y - mn[dq + 1];
        t[n][dq + 2] = f.z + NOISE_RATE * z.z - mn[dq + 2];
        t[n][dq + 3] = f.w + NOISE_RATE * z.w - mn[dq + 3];
    }
    __syncthreads();
    {
        int d = tid >> 3, nq = (tid & 7) * 4;
        float4 v = make_float4(t[nq + 0][d], t[nq + 1][d], t[nq + 2][d], t[nq + 3][d]);
        uint32_t h0, h1, m0, m1;
        split4(v, h0, h1, m0, m1);
        size_t off = ((size_t)(b * DIM + d0 + d)) * NPG + n0 + nq;
        *(uint2*)&DTh[off] = make_uint2(h0, h1);
        *(uint2*)&DTm[off] = make_uint2(m0, m1);
    }
}

// ---------------------------------------------------------------------------
// shared GEMM geometry (proven round-5/6 inner loop)
// ---------------------------------------------------------------------------
#define BM 128
#define BN 64
#define RSTRIDE 80
#define OFF_AH 0
#define OFF_AM (BM * RSTRIDE)
#define OFF_BH (2 * BM * RSTRIDE)
#define OFF_BM (2 * BM * RSTRIDE + BN * RSTRIDE)
#define SMEM_GEMM (2 * BM * RSTRIDE + 2 * BN * RSTRIDE)

#define GEMM_FRAG_SETUP()                                                         \
    uint32_t aAd[2];                                                              \
    _Pragma("unroll")                                                             \
    for (int mt = 0; mt < 2; mt++)                                                \
        aAd[mt] = sb + OFF_AH + (uint32_t)(wm + mt * 16 + (lane & 15)) * RSTRIDE  \
                + ((lane >> 4) & 1) * 16;                                         \
    uint32_t bAd[2];                                                              \
    _Pragma("unroll")                                                             \
    for (int p = 0; p < 2; p++)                                                   \
        bAd[p] = sb + OFF_BH + (uint32_t)(wn + p * 16 + (lane & 7) + ((lane >> 4) & 1) * 8) * RSTRIDE \
               + ((lane >> 3) & 1) * 16;

#define GEMM_MAINLOOP_CHUNK()                                                     \
    _Pragma("unroll")                                                             \
    for (int kk = 0; kk < 2; kk++) {                                              \
        uint32_t ah[2][4], am[2][4];                                              \
        _Pragma("unroll")                                                         \
        for (int mt = 0; mt < 2; mt++) {                                          \
            ldm4(ah[mt], aAd[mt] + kk * 32);                                      \
            ldm4(am[mt], aAd[mt] + kk * 32 + (OFF_AM - OFF_AH));                  \
        }                                                                         \
        {                                                                         \
            uint32_t bb[2][4];                                                    \
            _Pragma("unroll")                                                     \
            for (int p = 0; p < 2; p++) ldm4(bb[p], bAd[p] + kk * 32);            \
            _Pragma("unroll")                                                     \
            for (int mt = 0; mt < 2; mt++)                                        \
                _Pragma("unroll")                                                 \
                for (int nt = 0; nt < 4; nt++) {                                  \
                    mma16816(acc[mt][nt], ah[mt], &bb[nt >> 1][(nt & 1) * 2]);    \
                    mma16816(acc[mt][nt], am[mt], &bb[nt >> 1][(nt & 1) * 2]);    \
                }                                                                 \
        }                                                                         \
        {                                                                         \
            uint32_t bb[2][4];                                                    \
            _Pragma("unroll")                                                     \
            for (int p = 0; p < 2; p++) ldm4(bb[p], bAd[p] + kk * 32 + (OFF_BM - OFF_BH)); \
            _Pragma("unroll")                                                     \
            for (int mt = 0; mt < 2; mt++)                                        \
                _Pragma("unroll")                                                 \
                for (int nt = 0; nt < 4; nt++)                                    \
                    mma16816(acc[mt][nt], ah[mt], &bb[nt >> 1][(nt & 1) * 2]);    \
        }                                                                         \
    }

// ---------------------------------------------------------------------------
// batched 256x256x256 GEMM via bf16 split (fp32 operands, split on load).
// mode 0: C = A@B
// mode 1: C = 2.25*P - 1.5*Q + 0.25*(A@B)
// ---------------------------------------------------------------------------
__global__ void __launch_bounds__(256, 2) gemm_bf16(const float* __restrict__ Ag,
                                                    const float* __restrict__ Bg,
                                                    float* __restrict__ Cg,
                                                    const float* __restrict__ Pg,
                                                    const float* __restrict__ Qg,
                                                    int mode) {
    __shared__ char smem[SMEM_GEMM];
    const uint32_t sb = smem_u32(smem);
    const int tid = threadIdx.x, lane = tid & 31, wid = tid >> 5;
    const int b = blockIdx.z;
    const int m0 = blockIdx.y * BM, n0 = blockIdx.x * BN;
    const int wm = (wid & 3) * 32, wn = (wid >> 2) * 32;
    const float* A  = Ag + (size_t)b * DD;
    const float* Bm = Bg + (size_t)b * DD;

    const int srow = tid >> 3, skq = tid & 7;
    const float* gA = A  + (size_t)(m0 + srow) * DIM + skq * 4;
    const float* gB = Bm + (size_t)(n0 + srow) * DIM + skq * 4;
    const uint32_t stOff = (uint32_t)srow * RSTRIDE + skq * 8;

    GEMM_FRAG_SETUP();

    float acc[2][4][4];
    #pragma unroll
    for (int mt = 0; mt < 2; mt++)
        #pragma unroll
        for (int nt = 0; nt < 4; nt++)
            #pragma unroll
            for (int k = 0; k < 4; k++) acc[mt][nt][k] = 0.f;

    float4 pa[4], pb[2];
    #pragma unroll
    for (int p = 0; p < 4; p++) pa[p] = *(const float4*)(gA + (size_t)p * 32 * DIM);
    #pragma unroll
    for (int p = 0; p < 2; p++) pb[p] = *(const float4*)(gB + (size_t)p * 32 * DIM);

    for (int kc = 0; kc < 8; ++kc) {
        #pragma unroll
        for (int p = 0; p < 4; p++) {
            uint32_t h0, h1, q0, q1;
            split4(pa[p], h0, h1, q0, q1);
            uint32_t ad = stOff + p * 32 * RSTRIDE;
            *((uint2*)(smem + ad + OFF_AH)) = make_uint2(h0, h1);
            *((uint2*)(smem + ad + OFF_AM)) = make_uint2(q0, q1);
        }
        #pragma unroll
        for (int p = 0; p < 2; p++) {
            uint32_t h0, h1, q0, q1;
            split4(pb[p], h0, h1, q0, q1);
            uint32_t ad = stOff + p * 32 * RSTRIDE;
            *((uint2*)(smem + ad + OFF_BH)) = make_uint2(h0, h1);
            *((uint2*)(smem + ad + OFF_BM)) = make_uint2(q0, q1);
        }
        __syncthreads();
        if (kc < 7) {
            #pragma unroll
            for (int p = 0; p < 4; p++) pa[p] = *(const float4*)(gA + (size_t)p * 32 * DIM + (kc + 1) * 32);
            #pragma unroll
            for (int p = 0; p < 2; p++) pb[p] = *(const float4*)(gB + (size_t)p * 32 * DIM + (kc + 1) * 32);
        }
        GEMM_MAINLOOP_CHUNK();
        __syncthreads();
    }

    float* C = Cg + (size_t)b * DD;
    const float* P = Pg + (size_t)b * DD;
    const float* Q = Qg + (size_t)b * DD;
    int rr = m0 + wm + (lane >> 2);
    int cc = n0 + wn + (lane & 3) * 2;
    #pragma unroll
    for (int mt = 0; mt < 2; mt++) {
        #pragma unroll
        for (int nt = 0; nt < 4; nt++) {
            int r = rr + mt * 16, c = cc + nt * 8;
            float v0 = acc[mt][nt][0], v1 = acc[mt][nt][1];
            float v2 = acc[mt][nt][2], v3 = acc[mt][nt][3];
            if (mode == 1) {
                float2 p0 = *(const float2*)&P[(size_t)r * DIM + c];
                float2 p1 = *(const float2*)&P[(size_t)(r + 8) * DIM + c];
                float2 q0 = *(const float2*)&Q[(size_t)r * DIM + c];
                float2 q1 = *(const float2*)&Q[(size_t)(r + 8) * DIM + c];
                v0 = 2.25f * p0.x - 1.5f * q0.x + 0.25f * v0;
                v1 = 2.25f * p0.y - 1.5f * q0.y + 0.25f * v1;
                v2 = 2.25f * p1.x - 1.5f * q1.x + 0.25f * v2;
                v3 = 2.25f * p1.y - 1.5f * q1.y + 0.25f * v3;
            }
            *(float2*)&C[(size_t)r * DIM + c]       = make_float2(v0, v1);
            *(float2*)&C[(size_t)(r + 8) * DIM + c] = make_float2(v2, v3);
        }
    }
}

// ---------------------------------------------------------------------------
// covariance GEMM: A = (diff^T @ diff) / ((N-1)*trace), K = 512.
// ---------------------------------------------------------------------------
__global__ void __launch_bounds__(256, 2) cov_mma(const __nv_bfloat16* __restrict__ DTh,
                                                  const __nv_bfloat16* __restrict__ DTm,
                                                  float* __restrict__ Cg) {
    __shared__ char smem[SMEM_GEMM];
    const uint32_t sb = smem_u32(smem);
    const int tid = threadIdx.x, lane = tid & 31, wid = tid >> 5;
    const int b = blockIdx.z;
    const int m0 = blockIdx.y * BM, n0 = blockIdx.x * BN;
    const int wm = (wid & 3) * 32, wn = (wid >> 2) * 32;

    const int lrow = tid >> 2, lq = tid & 3;
    const __nv_bfloat16* baseH = DTh + (size_t)b * DIM * NPG;
    const __nv_bfloat16* baseM = DTm + (size_t)b * DIM * NPG;

    GEMM_FRAG_SETUP();

    float acc[2][4][4];
    #pragma unroll
    for (int mt = 0; mt < 2; mt++)
        #pragma unroll
        for (int nt = 0; nt < 4; nt++)
            #pragma unroll
            for (int k = 0; k < 4; k++) acc[mt][nt][k] = 0.f;

    uint4 pAh[2], pAm[2], pBh, pBm;
    {
        size_t a0 = (size_t)(m0 + lrow) * NPG + lq * 8;
        size_t a1 = (size_t)(m0 + 64 + lrow) * NPG + lq * 8;
        size_t b0 = (size_t)(n0 + lrow) * NPG + lq * 8;
        pAh[0] = *(const uint4*)(baseH + a0); pAm[0] = *(const uint4*)(baseM + a0);
        pAh[1] = *(const uint4*)(baseH + a1); pAm[1] = *(const uint4*)(baseM + a1);
        pBh    = *(const uint4*)(baseH + b0); pBm    = *(const uint4*)(baseM + b0);
    }

    for (int kc = 0; kc < 16; ++kc) {
        {
            uint32_t ad0 = (uint32_t)lrow * RSTRIDE + lq * 16;
            uint32_t ad1 = (uint32_t)(64 + lrow) * RSTRIDE + lq * 16;
            *((uint4*)(smem + ad0 + OFF_AH)) = pAh[0];
            *((uint4*)(smem + ad0 + OFF_AM)) = pAm[0];
            *((uint4*)(smem + ad1 + OFF_AH)) = pAh[1];
            *((uint4*)(smem + ad1 + OFF_AM)) = pAm[1];
            *((uint4*)(smem + ad0 + OFF_BH)) = pBh;
            *((uint4*)(smem + ad0 + OFF_BM)) = pBm;
        }
        __syncthreads();
        if (kc < 15) {
            size_t ko = (size_t)(kc + 1) * 32 + lq * 8;
            size_t a0 = (size_t)(m0 + lrow) * NPG + ko;
            size_t a1 = (size_t)(m0 + 64 + lrow) * NPG + ko;
            size_t b0 = (size_t)(n0 + lrow) * NPG + ko;
            pAh[0] = *(const uint4*)(baseH + a0); pAm[0] = *(const uint4*)(baseM + a0);
            pAh[1] = *(const uint4*)(baseH + a1); pAm[1] = *(const uint4*)(baseM + a1);
            pBh    = *(const uint4*)(baseH + b0); pBm    = *(const uint4*)(baseM + b0);
        }
        GEMM_MAINLOOP_CHUNK();
        __syncthreads();
    }

    float* C = Cg + (size_t)b * DD;
    const float sc = 1.f / ((NPG - 1) * g_norm[b]);
    int rr = m0 + wm + (lane >> 2);
    int cc = n0 + wn + (lane & 3) * 2;
    #pragma unroll
    for (int mt = 0; mt < 2; mt++) {
        #pragma unroll
        for (int nt = 0; nt < 4; nt++) {
            int r = rr + mt * 16, c = cc + nt * 8;
            *(float2*)&C[(size_t)r * DIM + c] =
                make_float2(acc[mt][nt][0] * sc, acc[mt][nt][1] * sc);
            *(float2*)&C[(size_t)(r + 8) * DIM + c] =
                make_float2(acc[mt][nt][2] * sc, acc[mt][nt][3] * sc);
        }
    }
}

// ---------------------------------------------------------------------------
// matvec: vout[b] = scale * (alpha*vin[b] + beta*(M[b] @ vin[b]))
// grid (8, NB): block handles 32 rows. vin != vout (ping-pong; cross-block safe).
// warp handles 4 rows; 8 lanes per row cover 32 cols each.
// ---------------------------------------------------------------------------
__global__ void matvec_kernel(const float* __restrict__ M,
                              const float* __restrict__ vin,
                              float* __restrict__ vout,
                              float alpha, float beta, int useScale) {
    int b = blockIdx.y;
    int r0 = blockIdx.x * 32;
    __shared__ float vs[DIM];
    int tid = threadIdx.x;
    vs[tid] = vin[b * DIM + tid];
    __syncthreads();
    int warp = tid >> 5, lane = tid & 31;
    int r = r0 + warp * 4 + (lane >> 3);
    int c0 = (lane & 7) * 32;
    const float* Mr = M + (size_t)b * DD + (size_t)r * DIM + c0;
    float s = 0.f;
    #pragma unroll
    for (int c = 0; c < 32; c += 4) {
        float4 mv = *(const float4*)(Mr + c);
        s += mv.x * vs[c0 + c] + mv.y * vs[c0 + c + 1]
           + mv.z * vs[c0 + c + 2] + mv.w * vs[c0 + c + 3];
    }
    #pragma unroll
    for (int o = 4; o; o >>= 1) s += __shfl_xor_sync(0xffffffffu, s, o);
    if ((lane & 7) == 0) {
        float scale = useScale ? sqrtf(g_norm[b]) : 1.f;
        vout[b * DIM + r] = scale * (alpha * vs[r] + beta * s);
    }
}

// ---------------------------------------------------------------------------
extern "C" void kernel_launch(void* const* d_in, const int* in_sizes, int n_in,
                              void* d_out, int out_size) {
    const float* feat  = (const float*)d_in[0];
    const float* noise = (const float*)d_in[1];
    float* out = (float*)d_out;

    float *A, *DTh, *DTm, *X2, *M0, *M1, *Mean, *Va, *Vb;
    cudaGetSymbolAddress((void**)&A,    g_A);
    cudaGetSymbolAddress((void**)&DTh,  g_DTh);
    cudaGetSymbolAddress((void**)&DTm,  g_DTm);
    cudaGetSymbolAddress((void**)&X2,   g_X2);
    cudaGetSymbolAddress((void**)&M0,   g_M0);
    cudaGetSymbolAddress((void**)&M1,   g_M1);
    cudaGetSymbolAddress((void**)&Mean, g_mean);
    cudaGetSymbolAddress((void**)&Va,   g_va);
    cudaGetSymbolAddress((void**)&Vb,   g_vb);

    mean_part<<<dim3(4, NB), 256>>>(feat, noise);
    mean_final<<<NB, 256>>>();
    prep_kernel<<<dim3(NPG / 32, DIM / 32, NB), 256>>>(feat, noise,
        (__nv_bfloat16*)DTh, (__nv_bfloat16*)DTm);
    cov_mma<<<dim3(DIM / BN, DIM / BM, NB), 256>>>(
        (const __nv_bfloat16*)DTh, (const __nv_bfloat16*)DTm, A);

    dim3 mv(8, NB);
    // v1 = 1.5*mean - 0.5*A@mean
    matvec_kernel<<<mv, 256>>>(A, Mean, Va, 1.5f, -0.5f, 0);

    // 4 applications of f(M) = 2.25M - 1.5M^2 + 0.25M^3 ; M_0 = A
    dim3 gg(DIM / BN, DIM / BM, NB);
    float* Mcur = A;
    float* Mbuf[2] = {M0, M1};
    float* Vbuf[2] = {Va, Vb};
    int vc = 0;
    for (int k = 0; k < 4; ++k) {
        float* Mnext = Mbuf[k & 1];
        gemm_bf16<<<gg, 256>>>(Mcur, Mcur, X2, A, A, 0);        // X2 = M@M
        gemm_bf16<<<gg, 256>>>(X2, Mcur, Mnext, Mcur, X2, 1);   // M' = f(M)
        matvec_kernel<<<mv, 256>>>(Mnext, Vbuf[vc], Vbuf[1 - vc], 1.5f, -0.5f, 0);
        vc ^= 1;
        Mcur = Mnext;
    }
    // out = sqrt(trace) * A @ u
    matvec_kernel<<<mv, 256>>>(A, Vbuf[vc], out, 0.f, 1.f, 1);
}

// round 9
// speedup vs baseline: 3.5619x; 1.1009x over previous
#include <cuda_runtime.h>
#include <cuda_bf16.h>
#include <math.h>
#include <stdint.h>

// Problem constants: feat [65536, 256], n_per_graph = 512 -> B = 128, d = 256.
#define NB   128
#define NPG  512
#define DIM  256
#define DD   (DIM*DIM)
#define BD   (NB*DD)
#define NOISE_RATE 0.01f

// Scratch (allocation-free rule: device globals)
__device__ float g_A[BD];      // A = cov/trace (fp32), preserved
__device__ float g_DTh[BD];    // reinterpreted as bf16 [B][DIM][NPG]: diff^T hi
__device__ float g_DTm[BD];    // reinterpreted as bf16 [B][DIM][NPG]: diff^T lo
__device__ float g_X2[BD];     // M^2 scratch
__device__ float g_M0[BD];     // M ping
__device__ float g_M1[BD];     // M pong
__device__ float g_mean[NB*DIM];
__device__ float g_va[NB*DIM];
__device__ float g_vb[NB*DIM];
__device__ float g_norm[NB];
__device__ float g_psum[NB*4*DIM];
__device__ float g_psq[NB*4*DIM];

// ---------------------------------------------------------------------------
// helpers
// ---------------------------------------------------------------------------
__device__ __forceinline__ uint32_t smem_u32(const void* p) {
    uint32_t a;
    asm("{ .reg .u64 t; cvta.to.shared.u64 t, %1; cvt.u32.u64 %0, t; }" : "=r"(a) : "l"(p));
    return a;
}
__device__ __forceinline__ void ldm4(uint32_t* r, uint32_t a) {
    asm volatile("ldmatrix.sync.aligned.m8n8.x4.shared.b16 {%0,%1,%2,%3}, [%4];"
                 : "=r"(r[0]), "=r"(r[1]), "=r"(r[2]), "=r"(r[3]) : "r"(a));
}
__device__ __forceinline__ void mma16816(float* c, const uint32_t* a, const uint32_t* bq) {
    asm volatile("mma.sync.aligned.m16n8k16.row.col.f32.bf16.bf16.f32 "
                 "{%0,%1,%2,%3}, {%4,%5,%6,%7}, {%8,%9}, {%0,%1,%2,%3};"
                 : "+f"(c[0]), "+f"(c[1]), "+f"(c[2]), "+f"(c[3])
                 : "r"(a[0]), "r"(a[1]), "r"(a[2]), "r"(a[3]), "r"(bq[0]), "r"(bq[1]));
}
// bf16 2-term split of 4 floats -> packed h (2x u32) and m (2x u32)
__device__ __forceinline__ void split4(float4 v, uint32_t& h0, uint32_t& h1,
                                       uint32_t& q0, uint32_t& q1) {
    __nv_bfloat16 a = __float2bfloat16_rn(v.x);
    __nv_bfloat16 bb = __float2bfloat16_rn(v.y);
    __nv_bfloat16 c = __float2bfloat16_rn(v.z);
    __nv_bfloat16 d = __float2bfloat16_rn(v.w);
    __nv_bfloat162 hl; hl.x = a;  hl.y = bb;
    __nv_bfloat162 hh; hh.x = c;  hh.y = d;
    h0 = *(uint32_t*)&hl; h1 = *(uint32_t*)&hh;
    __nv_bfloat16 ma = __float2bfloat16_rn(v.x - __bfloat162float(a));
    __nv_bfloat16 mb = __float2bfloat16_rn(v.y - __bfloat162float(bb));
    __nv_bfloat16 mc = __float2bfloat16_rn(v.z - __bfloat162float(c));
    __nv_bfloat16 md = __float2bfloat16_rn(v.w - __bfloat162float(d));
    __nv_bfloat162 ml; ml.x = ma; ml.y = mb;
    __nv_bfloat162 mh; mh.x = mc; mh.y = md;
    q0 = *(uint32_t*)&ml; q1 = *(uint32_t*)&mh;
}

// symmetric-output tile map: 6 tiles cover the 2x4 (BM=128 x BN=64) grid of a
// 256x256 symmetric matrix. Tiles 2,3 are strictly upper -> mirror into lower.
__device__ __forceinline__ void sym_tile(int bx, int& mi, int& nj, int& mirror) {
    // list: (0,0) (0,1) (0,2)* (0,3)* (1,2) (1,3)
    mi = (bx >= 4) ? 1 : 0;
    nj = (bx >= 4) ? (bx - 2) : bx;
    mirror = (bx == 2 || bx == 3) ? 1 : 0;
}

// ---------------------------------------------------------------------------
// mean stage 1: grid (4, NB), block 256: partial sum + sumsq over 128 nodes
// ---------------------------------------------------------------------------
__global__ void mean_part(const float* __restrict__ feat,
                          const float* __restrict__ noise) {
    int b = blockIdx.y, p = blockIdx.x, c = threadIdx.x;
    const float* F  = feat  + ((size_t)b * NPG + p * 128) * DIM + c;
    const float* Nz = noise + ((size_t)b * NPG + p * 128) * DIM + c;
    float s = 0.f, q = 0.f;
    #pragma unroll 8
    for (int n = 0; n < 128; ++n) {
        float v = F[(size_t)n * DIM] + NOISE_RATE * Nz[(size_t)n * DIM];
        s += v; q += v * v;
    }
    g_psum[(b * 4 + p) * DIM + c] = s;
    g_psq [(b * 4 + p) * DIM + c] = q;
}

// mean stage 2: grid NB, block 256: finalize mean + trace
__global__ void mean_final() {
    int b = blockIdx.x, c = threadIdx.x;
    float s = 0.f, q = 0.f;
    #pragma unroll
    for (int p = 0; p < 4; ++p) {
        s += g_psum[(b * 4 + p) * DIM + c];
        q += g_psq [(b * 4 + p) * DIM + c];
    }
    float m = s * (1.f / NPG);
    g_mean[b * DIM + c] = m;
    float t = q - (float)NPG * m * m;
    #pragma unroll
    for (int o = 16; o; o >>= 1) t += __shfl_xor_sync(0xffffffffu, t, o);
    __shared__ float sm[8];
    if ((c & 31) == 0) sm[c >> 5] = t;
    __syncthreads();
    if (c == 0) {
        float tot = 0.f;
        #pragma unroll
        for (int w = 0; w < 8; w++) tot += sm[w];
        g_norm[b] = tot * (1.f / (NPG - 1));
    }
}

// ---------------------------------------------------------------------------
// prep: diff^T split to bf16 (h, m), transposed to [b][dim][node].
// ---------------------------------------------------------------------------
__global__ void prep_kernel(const float* __restrict__ feat,
                            const float* __restrict__ noise,
                            __nv_bfloat16* __restrict__ DTh,
                            __nv_bfloat16* __restrict__ DTm) {
    int b = blockIdx.z;
    int n0 = blockIdx.x * 32, d0 = blockIdx.y * 32;
    __shared__ float t[32][33];
    __shared__ float mn[32];
    int tid = threadIdx.x;
    if (tid < 32) mn[tid] = g_mean[b * DIM + d0 + tid];
    __syncthreads();
    {
        int n = tid >> 3, dq = (tid & 7) * 4;
        size_t off = ((size_t)(b * NPG + n0 + n)) * DIM + d0 + dq;
        float4 f = *(const float4*)&feat[off];
        float4 z = *(const float4*)&noise[off];
        t[n][dq + 0] = f.x + NOISE_RATE * z.x - mn[dq + 0];
        t[n][dq + 1] = f.y + NOISE_RATE * z.y - mn[dq + 1];
        t[n][dq + 2] = f.z + NOISE_RATE * z.z - mn[dq + 2];
        t[n][dq + 3] = f.w + NOISE_RATE * z.w - mn[dq + 3];
    }
    __syncthreads();
    {
        int d = tid >> 3, nq = (tid & 7) * 4;
        float4 v = make_float4(t[nq + 0][d], t[nq + 1][d], t[nq + 2][d], t[nq + 3][d]);
        uint32_t h0, h1, m0, m1;
        split4(v, h0, h1, m0, m1);
        size_t off = ((size_t)(b * DIM + d0 + d)) * NPG + n0 + nq;
        *(uint2*)&DTh[off] = make_uint2(h0, h1);
        *(uint2*)&DTm[off] = make_uint2(m0, m1);
    }
}

// ---------------------------------------------------------------------------
// shared GEMM geometry (proven round-5/6 inner loop)
// ---------------------------------------------------------------------------
#define BM 128
#define BN 64
#define RSTRIDE 80
#define OFF_AH 0
#define OFF_AM (BM * RSTRIDE)
#define OFF_BH (2 * BM * RSTRIDE)
#define OFF_BM (2 * BM * RSTRIDE + BN * RSTRIDE)
#define SMEM_GEMM (2 * BM * RSTRIDE + 2 * BN * RSTRIDE)

#define GEMM_FRAG_SETUP()                                                         \
    uint32_t aAd[2];                                                              \
    _Pragma("unroll")                                                             \
    for (int mt = 0; mt < 2; mt++)                                                \
        aAd[mt] = sb + OFF_AH + (uint32_t)(wm + mt * 16 + (lane & 15)) * RSTRIDE  \
                + ((lane >> 4) & 1) * 16;                                         \
    uint32_t bAd[2];                                                              \
    _Pragma("unroll")                                                             \
    for (int p = 0; p < 2; p++)                                                   \
        bAd[p] = sb + OFF_BH + (uint32_t)(wn + p * 16 + (lane & 7) + ((lane >> 4) & 1) * 8) * RSTRIDE \
               + ((lane >> 3) & 1) * 16;

#define GEMM_MAINLOOP_CHUNK()                                                     \
    _Pragma("unroll")                                                             \
    for (int kk = 0; kk < 2; kk++) {                                              \
        uint32_t ah[2][4], am[2][4];                                              \
        _Pragma("unroll")                                                         \
        for (int mt = 0; mt < 2; mt++) {                                          \
            ldm4(ah[mt], aAd[mt] + kk * 32);                                      \
            ldm4(am[mt], aAd[mt] + kk * 32 + (OFF_AM - OFF_AH));                  \
        }                                                                         \
        {                                                                         \
            uint32_t bb[2][4];                                                    \
            _Pragma("unroll")                                                     \
            for (int p = 0; p < 2; p++) ldm4(bb[p], bAd[p] + kk * 32);            \
            _Pragma("unroll")                                                     \
            for (int mt = 0; mt < 2; mt++)                                        \
                _Pragma("unroll")                                                 \
                for (int nt = 0; nt < 4; nt++) {                                  \
                    mma16816(acc[mt][nt], ah[mt], &bb[nt >> 1][(nt & 1) * 2]);    \
                    mma16816(acc[mt][nt], am[mt], &bb[nt >> 1][(nt & 1) * 2]);    \
                }                                                                 \
        }                                                                         \
        {                                                                         \
            uint32_t bb[2][4];                                                    \
            _Pragma("unroll")                                                     \
            for (int p = 0; p < 2; p++) ldm4(bb[p], bAd[p] + kk * 32 + (OFF_BM - OFF_BH)); \
            _Pragma("unroll")                                                     \
            for (int mt = 0; mt < 2; mt++)                                        \
                _Pragma("unroll")                                                 \
                for (int nt = 0; nt < 4; nt++)                                    \
                    mma16816(acc[mt][nt], ah[mt], &bb[nt >> 1][(nt & 1) * 2]);    \
        }                                                                         \
    }

// ---------------------------------------------------------------------------
// batched symmetric 256x256x256 GEMM via bf16 split.
// Output is symmetric: 6 tiles computed, upper-strict tiles mirrored to lower.
// mode 0: C = A@B
// mode 1: C = 2.25*P - 1.5*Q + 0.25*(A@B)
// ---------------------------------------------------------------------------
__global__ void __launch_bounds__(256, 2) gemm_bf16(const float* __restrict__ Ag,
                                                    const float* __restrict__ Bg,
                                                    float* __restrict__ Cg,
                                                    const float* __restrict__ Pg,
                                                    const float* __restrict__ Qg,
                                                    int mode) {
    __shared__ char smem[SMEM_GEMM];
    const uint32_t sb = smem_u32(smem);
    const int tid = threadIdx.x, lane = tid & 31, wid = tid >> 5;
    const int b = blockIdx.z;
    int mi, nj, mirror;
    sym_tile(blockIdx.x, mi, nj, mirror);
    const int m0 = mi * BM, n0 = nj * BN;
    const int wm = (wid & 3) * 32, wn = (wid >> 2) * 32;
    const float* A  = Ag + (size_t)b * DD;
    const float* Bm = Bg + (size_t)b * DD;

    const int srow = tid >> 3, skq = tid & 7;
    const float* gA = A  + (size_t)(m0 + srow) * DIM + skq * 4;
    const float* gB = Bm + (size_t)(n0 + srow) * DIM + skq * 4;
    const uint32_t stOff = (uint32_t)srow * RSTRIDE + skq * 8;

    GEMM_FRAG_SETUP();

    float acc[2][4][4];
    #pragma unroll
    for (int mt = 0; mt < 2; mt++)
        #pragma unroll
        for (int nt = 0; nt < 4; nt++)
            #pragma unroll
            for (int k = 0; k < 4; k++) acc[mt][nt][k] = 0.f;

    float4 pa[4], pb[2];
    #pragma unroll
    for (int p = 0; p < 4; p++) pa[p] = *(const float4*)(gA + (size_t)p * 32 * DIM);
    #pragma unroll
    for (int p = 0; p < 2; p++) pb[p] = *(const float4*)(gB + (size_t)p * 32 * DIM);

    for (int kc = 0; kc < 8; ++kc) {
        #pragma unroll
        for (int p = 0; p < 4; p++) {
            uint32_t h0, h1, q0, q1;
            split4(pa[p], h0, h1, q0, q1);
            uint32_t ad = stOff + p * 32 * RSTRIDE;
            *((uint2*)(smem + ad + OFF_AH)) = make_uint2(h0, h1);
            *((uint2*)(smem + ad + OFF_AM)) = make_uint2(q0, q1);
        }
        #pragma unroll
        for (int p = 0; p < 2; p++) {
            uint32_t h0, h1, q0, q1;
            split4(pb[p], h0, h1, q0, q1);
            uint32_t ad = stOff + p * 32 * RSTRIDE;
            *((uint2*)(smem + ad + OFF_BH)) = make_uint2(h0, h1);
            *((uint2*)(smem + ad + OFF_BM)) = make_uint2(q0, q1);
        }
        __syncthreads();
        if (kc < 7) {
            #pragma unroll
            for (int p = 0; p < 4; p++) pa[p] = *(const float4*)(gA + (size_t)p * 32 * DIM + (kc + 1) * 32);
            #pragma unroll
            for (int p = 0; p < 2; p++) pb[p] = *(const float4*)(gB + (size_t)p * 32 * DIM + (kc + 1) * 32);
        }
        GEMM_MAINLOOP_CHUNK();
        __syncthreads();
    }

    float* C = Cg + (size_t)b * DD;
    const float* P = Pg + (size_t)b * DD;
    const float* Q = Qg + (size_t)b * DD;
    int rr = m0 + wm + (lane >> 2);
    int cc = n0 + wn + (lane & 3) * 2;
    #pragma unroll
    for (int mt = 0; mt < 2; mt++) {
        #pragma unroll
        for (int nt = 0; nt < 4; nt++) {
            int r = rr + mt * 16, c = cc + nt * 8;
            float v0 = acc[mt][nt][0], v1 = acc[mt][nt][1];
            float v2 = acc[mt][nt][2], v3 = acc[mt][nt][3];
            if (mode == 1) {
                float2 p0 = *(const float2*)&P[(size_t)r * DIM + c];
                float2 p1 = *(const float2*)&P[(size_t)(r + 8) * DIM + c];
                float2 q0 = *(const float2*)&Q[(size_t)r * DIM + c];
                float2 q1 = *(const float2*)&Q[(size_t)(r + 8) * DIM + c];
                v0 = 2.25f * p0.x - 1.5f * q0.x + 0.25f * v0;
                v1 = 2.25f * p0.y - 1.5f * q0.y + 0.25f * v1;
                v2 = 2.25f * p1.x - 1.5f * q1.x + 0.25f * v2;
                v3 = 2.25f * p1.y - 1.5f * q1.y + 0.25f * v3;
            }
            *(float2*)&C[(size_t)r * DIM + c]       = make_float2(v0, v1);
            *(float2*)&C[(size_t)(r + 8) * DIM + c] = make_float2(v2, v3);
            if (mirror) {
                C[(size_t)(c + 0) * DIM + r]     = v0;
                C[(size_t)(c + 1) * DIM + r]     = v1;
                C[(size_t)(c + 0) * DIM + r + 8] = v2;
                C[(size_t)(c + 1) * DIM + r + 8] = v3;
            }
        }
    }
}

// ---------------------------------------------------------------------------
// covariance GEMM: A = (diff^T @ diff) / ((N-1)*trace), K = 512. Symmetric.
// ---------------------------------------------------------------------------
__global__ void __launch_bounds__(256, 2) cov_mma(const __nv_bfloat16* __restrict__ DTh,
                                                  const __nv_bfloat16* __restrict__ DTm,
                                                  float* __restrict__ Cg) {
    __shared__ char smem[SMEM_GEMM];
    const uint32_t sb = smem_u32(smem);
    const int tid = threadIdx.x, lane = tid & 31, wid = tid >> 5;
    const int b = blockIdx.z;
    int mi, nj, mirror;
    sym_tile(blockIdx.x, mi, nj, mirror);
    const int m0 = mi * BM, n0 = nj * BN;
    const int wm = (wid & 3) * 32, wn = (wid >> 2) * 32;

    const int lrow = tid >> 2, lq = tid & 3;
    const __nv_bfloat16* baseH = DTh + (size_t)b * DIM * NPG;
    const __nv_bfloat16* baseM = DTm + (size_t)b * DIM * NPG;

    GEMM_FRAG_SETUP();

    float acc[2][4][4];
    #pragma unroll
    for (int mt = 0; mt < 2; mt++)
        #pragma unroll
        for (int nt = 0; nt < 4; nt++)
            #pragma unroll
            for (int k = 0; k < 4; k++) acc[mt][nt][k] = 0.f;

    uint4 pAh[2], pAm[2], pBh, pBm;
    {
        size_t a0 = (size_t)(m0 + lrow) * NPG + lq * 8;
        size_t a1 = (size_t)(m0 + 64 + lrow) * NPG + lq * 8;
        size_t b0 = (size_t)(n0 + lrow) * NPG + lq * 8;
        pAh[0] = *(const uint4*)(baseH + a0); pAm[0] = *(const uint4*)(baseM + a0);
        pAh[1] = *(const uint4*)(baseH + a1); pAm[1] = *(const uint4*)(baseM + a1);
        pBh    = *(const uint4*)(baseH + b0); pBm    = *(const uint4*)(baseM + b0);
    }

    for (int kc = 0; kc < 16; ++kc) {
        {
            uint32_t ad0 = (uint32_t)lrow * RSTRIDE + lq * 16;
            uint32_t ad1 = (uint32_t)(64 + lrow) * RSTRIDE + lq * 16;
            *((uint4*)(smem + ad0 + OFF_AH)) = pAh[0];
            *((uint4*)(smem + ad0 + OFF_AM)) = pAm[0];
            *((uint4*)(smem + ad1 + OFF_AH)) = pAh[1];
            *((uint4*)(smem + ad1 + OFF_AM)) = pAm[1];
            *((uint4*)(smem + ad0 + OFF_BH)) = pBh;
            *((uint4*)(smem + ad0 + OFF_BM)) = pBm;
        }
        __syncthreads();
        if (kc < 15) {
            size_t ko = (size_t)(kc + 1) * 32 + lq * 8;
            size_t a0 = (size_t)(m0 + lrow) * NPG + ko;
            size_t a1 = (size_t)(m0 + 64 + lrow) * NPG + ko;
            size_t b0 = (size_t)(n0 + lrow) * NPG + ko;
            pAh[0] = *(const uint4*)(baseH + a0); pAm[0] = *(const uint4*)(baseM + a0);
            pAh[1] = *(const uint4*)(baseH + a1); pAm[1] = *(const uint4*)(baseM + a1);
            pBh    = *(const uint4*)(baseH + b0); pBm    = *(const uint4*)(baseM + b0);
        }
        GEMM_MAINLOOP_CHUNK();
        __syncthreads();
    }

    float* C = Cg + (size_t)b * DD;
    const float sc = 1.f / ((NPG - 1) * g_norm[b]);
    int rr = m0 + wm + (lane >> 2);
    int cc = n0 + wn + (lane & 3) * 2;
    #pragma unroll
    for (int mt = 0; mt < 2; mt++) {
        #pragma unroll
        for (int nt = 0; nt < 4; nt++) {
            int r = rr + mt * 16, c = cc + nt * 8;
            float v0 = acc[mt][nt][0] * sc, v1 = acc[mt][nt][1] * sc;
            float v2 = acc[mt][nt][2] * sc, v3 = acc[mt][nt][3] * sc;
            *(float2*)&C[(size_t)r * DIM + c]       = make_float2(v0, v1);
            *(float2*)&C[(size_t)(r + 8) * DIM + c] = make_float2(v2, v3);
            if (mirror) {
                C[(size_t)(c + 0) * DIM + r]     = v0;
                C[(size_t)(c + 1) * DIM + r]     = v1;
                C[(size_t)(c + 0) * DIM + r + 8] = v2;
                C[(size_t)(c + 1) * DIM + r + 8] = v3;
            }
        }
    }
}

// ---------------------------------------------------------------------------
// matvec: vout[b] = scale * (alpha*vin[b] + beta*(M[b] @ vin[b]))
// grid (8, NB): block handles 32 rows. vin != vout (ping-pong).
// ---------------------------------------------------------------------------
__global__ void matvec_kernel(const float* __restrict__ M,
                              const float* __restrict__ vin,
                              float* __restrict__ vout,
                              float alpha, float beta, int useScale) {
    int b = blockIdx.y;
    int r0 = blockIdx.x * 32;
    __shared__ float vs[DIM];
    int tid = threadIdx.x;
    vs[tid] = vin[b * DIM + tid];
    __syncthreads();
    int warp = tid >> 5, lane = tid & 31;
    int r = r0 + warp * 4 + (lane >> 3);
    int c0 = (lane & 7) * 32;
    const float* Mr = M + (size_t)b * DD + (size_t)r * DIM + c0;
    float s = 0.f;
    #pragma unroll
    for (int c = 0; c < 32; c += 4) {
        float4 mv = *(const float4*)(Mr + c);
        s += mv.x * vs[c0 + c] + mv.y * vs[c0 + c + 1]
           + mv.z * vs[c0 + c + 2] + mv.w * vs[c0 + c + 3];
    }
    #pragma unroll
    for (int o = 4; o; o >>= 1) s += __shfl_xor_sync(0xffffffffu, s, o);
    if ((lane & 7) == 0) {
        float scale = useScale ? sqrtf(g_norm[b]) : 1.f;
        vout[b * DIM + r] = scale * (alpha * vs[r] + beta * s);
    }
}

// ---------------------------------------------------------------------------
extern "C" void kernel_launch(void* const* d_in, const int* in_sizes, int n_in,
                              void* d_out, int out_size) {
    const float* feat  = (const float*)d_in[0];
    const float* noise = (const float*)d_in[1];
    float* out = (float*)d_out;

    float *A, *DTh, *DTm, *X2, *M0, *M1, *Mean, *Va, *Vb;
    cudaGetSymbolAddress((void**)&A,    g_A);
    cudaGetSymbolAddress((void**)&DTh,  g_DTh);
    cudaGetSymbolAddress((void**)&DTm,  g_DTm);
    cudaGetSymbolAddress((void**)&X2,   g_X2);
    cudaGetSymbolAddress((void**)&M0,   g_M0);
    cudaGetSymbolAddress((void**)&M1,   g_M1);
    cudaGetSymbolAddress((void**)&Mean, g_mean);
    cudaGetSymbolAddress((void**)&Va,   g_va);
    cudaGetSymbolAddress((void**)&Vb,   g_vb);

    mean_part<<<dim3(4, NB), 256>>>(feat, noise);
    mean_final<<<NB, 256>>>();
    prep_kernel<<<dim3(NPG / 32, DIM / 32, NB), 256>>>(feat, noise,
        (__nv_bfloat16*)DTh, (__nv_bfloat16*)DTm);
    cov_mma<<<dim3(6, 1, NB), 256>>>(
        (const __nv_bfloat16*)DTh, (const __nv_bfloat16*)DTm, A);

    dim3 mv(8, NB);
    // v1 = 1.5*mean - 0.5*A@mean
    matvec_kernel<<<mv, 256>>>(A, Mean, Va, 1.5f, -0.5f, 0);

    // 4 applications of f(M) = 2.25M - 1.5M^2 + 0.25M^3 ; M_0 = A
    dim3 gg(6, 1, NB);
    float* Mcur = A;
    float* Mbuf[2] = {M0, M1};
    float* Vbuf[2] = {Va, Vb};
    int vc = 0;
    for (int k = 0; k < 4; ++k) {
        float* Mnext = Mbuf[k & 1];
        gemm_bf16<<<gg, 256>>>(Mcur, Mcur, X2, A, A, 0);        // X2 = M@M
        gemm_bf16<<<gg, 256>>>(X2, Mcur, Mnext, Mcur, X2, 1);   // M' = f(M)
        matvec_kernel<<<mv, 256>>>(Mnext, Vbuf[vc], Vbuf[1 - vc], 1.5f, -0.5f, 0);
        vc ^= 1;
        Mcur = Mnext;
    }
    // out = sqrt(trace) * A @ u
    matvec_kernel<<<mv, 256>>>(A, Vbuf[vc], out, 0.f, 1.f, 1);
}